// round 7
// baseline (speedup 1.0000x reference)
#include <cuda_runtime.h>
#include <cstddef>

static constexpr int    N_  = 3072;
static constexpr int    C_  = 256;
static constexpr int    H_  = 4;
static constexpr int    D_  = 64;
static constexpr size_t HS_ = (size_t)N_ * N_;      // head stride in attn
static constexpr size_t QS_ = (size_t)N_ * D_;      // head stride in q/k/v

// ---------------- device scratch (module-load allocated, rule-compliant) ----------------
__device__ float g_regp   [N_ * C_];
__device__ float g_qkv_cls[N_ * 3 * C_];
__device__ float g_qkv_reg[N_ * 3 * C_];
__device__ float g_qn_cls [H_ * N_ * D_];
__device__ float g_kn_cls [H_ * N_ * D_];
__device__ float g_v_cls  [H_ * N_ * D_];
__device__ float g_qn_reg [H_ * N_ * D_];
__device__ float g_kn_reg [H_ * N_ * D_];
__device__ float g_v_reg  [H_ * N_ * D_];
__device__ float g_vnf_cls[N_ * C_];
__device__ float g_vnf_reg[N_ * C_];
__device__ float g_bufA[(size_t)H_ * N_ * N_];   // logits_cls -> averaged attn (in place)
__device__ float g_bufB[(size_t)H_ * N_ * N_];   // logits_reg -> later gram_cls | gram_reg
__device__ float g_sr2 [(size_t)N_ * N_];
__device__ float g_obj [(size_t)N_ * N_];
__device__ float g_enh_cls[N_ * 2 * C_];
__device__ float g_enh_reg[N_ * 2 * C_];
__device__ float g_pool_cls[N_ * 4 * C_];
__device__ float g_pool_reg[N_ * 4 * C_];

// ---------------- packed f32x2 helpers (Blackwell; FFMA2 only via PTX) ----------------
#define FMA2(d, a, b) \
    asm("fma.rn.f32x2 %0, %1, %2, %0;" : "+l"(d) : "l"(a), "l"(b))
#define PACK_DUP(d, x) \
    asm("mov.b64 %0, {%1, %1};" : "=l"(d) : "f"(x))
#define UNPACK2(x, y, d) \
    asm("mov.b64 {%0, %1}, %2;" : "=f"(x), "=f"(y) : "l"(d))

// =======================================================================================
// Double-buffered, register-staged tiled SGEMM with packed-f32x2 (FFMA2) inner loop.
//   C[M,N] = alpha * A[M,K] x op(B) (+ bias[col])
//   TRANSB = true : B is [N,K] row-major (x @ W^T)
//   TRANSB = false: B is [K,N] row-major (NN)
// Tile: BM = 64*MB, BN = 64*NB, BK = 16; 256 threads; microtile (4*MB)x(4*NB).
// REQUIRES: M % BM == 0, N % BN == 0, K % BK == 0 (true for every call here).
// Batched via gridDim.z with element strides sA/sB/sC.
// =======================================================================================
template <bool TRANSB, int MB, int NB>
__global__ __launch_bounds__(256)
void gemm_kernel(int K,
                 const float* __restrict__ A, int lda, size_t sA,
                 const float* __restrict__ B, int ldb, size_t sB,
                 float* __restrict__ C, int ldc, size_t sC,
                 float alpha, const float* __restrict__ bias)
{
    constexpr int BM = 64 * MB, BN = 64 * NB, BK = 16;
    __shared__ float As[2][BK][BM];
    __shared__ float Bs[2][BK][BN];

    const int bz = blockIdx.z;
    A += (size_t)bz * sA;
    B += (size_t)bz * sB;
    C += (size_t)bz * sC;

    const int m0  = blockIdx.y * BM;
    const int n0  = blockIdx.x * BN;
    const int tid = threadIdx.x;
    const int tx  = tid & 15;
    const int ty  = tid >> 4;

    // ---- per-chunk load coordinates (computed once) ----
    int a_m[MB], a_k[MB];
    const float* aPtr[MB];
#pragma unroll
    for (int i = 0; i < MB; i++) {
        int id = tid + i * 256;
        a_m[i] = id >> 2;
        a_k[i] = (id & 3) << 2;
        aPtr[i] = A + (size_t)(m0 + a_m[i]) * lda + a_k[i];
    }

    int b_r[NB], b_c[NB];           // smem (row=k, col=n) coords of this chunk
    const float* bPtr[NB];
#pragma unroll
    for (int i = 0; i < NB; i++) {
        int id = tid + i * 256;
        if (TRANSB) {
            b_c[i] = id >> 2;               // n
            b_r[i] = (id & 3) << 2;         // k quad base
            bPtr[i] = B + (size_t)(n0 + b_c[i]) * ldb + b_r[i];
        } else {
            b_r[i] = id / (16 * NB);        // k
            b_c[i] = (id % (16 * NB)) << 2; // n quad base
            bPtr[i] = B + (size_t)b_r[i] * ldb + n0 + b_c[i];
        }
    }

    // packed accumulators: acc2[mi][ni][i][p] = (c[i][2p], c[i][2p+1])
    unsigned long long acc2[MB][NB][4][2];
#pragma unroll
    for (int a = 0; a < MB; a++)
#pragma unroll
        for (int b = 0; b < NB; b++)
#pragma unroll
            for (int i = 0; i < 4; i++)
#pragma unroll
                for (int p = 0; p < 2; p++) acc2[a][b][i][p] = 0ull;

    float4 avr[MB], bvr[NB];

    // ---- prologue: load + store stage 0 ----
#pragma unroll
    for (int i = 0; i < MB; i++) avr[i] = *reinterpret_cast<const float4*>(aPtr[i]);
#pragma unroll
    for (int i = 0; i < NB; i++) bvr[i] = *reinterpret_cast<const float4*>(bPtr[i]);

#pragma unroll
    for (int i = 0; i < MB; i++) {
        As[0][a_k[i] + 0][a_m[i]] = avr[i].x;
        As[0][a_k[i] + 1][a_m[i]] = avr[i].y;
        As[0][a_k[i] + 2][a_m[i]] = avr[i].z;
        As[0][a_k[i] + 3][a_m[i]] = avr[i].w;
    }
#pragma unroll
    for (int i = 0; i < NB; i++) {
        if (TRANSB) {
            Bs[0][b_r[i] + 0][b_c[i]] = bvr[i].x;
            Bs[0][b_r[i] + 1][b_c[i]] = bvr[i].y;
            Bs[0][b_r[i] + 2][b_c[i]] = bvr[i].z;
            Bs[0][b_r[i] + 3][b_c[i]] = bvr[i].w;
        } else {
            *reinterpret_cast<float4*>(&Bs[0][b_r[i]][b_c[i]]) = bvr[i];
        }
    }
    __syncthreads();

    int buf = 0;
    for (int k0 = 0; k0 < K; k0 += BK) {
        const bool has_next = (k0 + BK) < K;

        // issue global loads for the next stage early (latency overlap)
        if (has_next) {
#pragma unroll
            for (int i = 0; i < MB; i++)
                avr[i] = *reinterpret_cast<const float4*>(aPtr[i] + (k0 + BK));
            if (TRANSB) {
#pragma unroll
                for (int i = 0; i < NB; i++)
                    bvr[i] = *reinterpret_cast<const float4*>(bPtr[i] + (k0 + BK));
            } else {
#pragma unroll
                for (int i = 0; i < NB; i++)
                    bvr[i] = *reinterpret_cast<const float4*>(bPtr[i] + (size_t)(k0 + BK) * ldb);
            }
        }

        // compute current stage (packed f32x2 FMAs)
#pragma unroll
        for (int kk = 0; kk < BK; kk++) {
            float a[MB][4];
            ulonglong2 bq[NB];
#pragma unroll
            for (int mi = 0; mi < MB; mi++)
                *reinterpret_cast<float4*>(a[mi]) =
                    *reinterpret_cast<const float4*>(&As[buf][kk][ty * 4 + mi * 64]);
#pragma unroll
            for (int ni = 0; ni < NB; ni++)
                bq[ni] = *reinterpret_cast<const ulonglong2*>(&Bs[buf][kk][tx * 4 + ni * 64]);

            unsigned long long adup[MB][4];
#pragma unroll
            for (int mi = 0; mi < MB; mi++)
#pragma unroll
                for (int i = 0; i < 4; i++)
                    PACK_DUP(adup[mi][i], a[mi][i]);

#pragma unroll
            for (int mi = 0; mi < MB; mi++)
#pragma unroll
                for (int ni = 0; ni < NB; ni++)
#pragma unroll
                    for (int i = 0; i < 4; i++) {
                        FMA2(acc2[mi][ni][i][0], adup[mi][i], bq[ni].x);
                        FMA2(acc2[mi][ni][i][1], adup[mi][i], bq[ni].y);
                    }
        }

        // store next stage into the other buffer
        if (has_next) {
            int nb = buf ^ 1;
#pragma unroll
            for (int i = 0; i < MB; i++) {
                As[nb][a_k[i] + 0][a_m[i]] = avr[i].x;
                As[nb][a_k[i] + 1][a_m[i]] = avr[i].y;
                As[nb][a_k[i] + 2][a_m[i]] = avr[i].z;
                As[nb][a_k[i] + 3][a_m[i]] = avr[i].w;
            }
#pragma unroll
            for (int i = 0; i < NB; i++) {
                if (TRANSB) {
                    Bs[nb][b_r[i] + 0][b_c[i]] = bvr[i].x;
                    Bs[nb][b_r[i] + 1][b_c[i]] = bvr[i].y;
                    Bs[nb][b_r[i] + 2][b_c[i]] = bvr[i].z;
                    Bs[nb][b_r[i] + 3][b_c[i]] = bvr[i].w;
                } else {
                    *reinterpret_cast<float4*>(&Bs[nb][b_r[i]][b_c[i]]) = bvr[i];
                }
            }
            __syncthreads();
            buf = nb;
        }
    }

    // ---- epilogue ----
#pragma unroll
    for (int mi = 0; mi < MB; mi++)
#pragma unroll
        for (int i = 0; i < 4; i++) {
            int r = m0 + mi * 64 + ty * 4 + i;
            float* crow = C + (size_t)r * ldc;
#pragma unroll
            for (int ni = 0; ni < NB; ni++) {
                int cb = n0 + ni * 64 + tx * 4;
                float c0, c1, c2, c3;
                UNPACK2(c0, c1, acc2[mi][ni][i][0]);
                UNPACK2(c2, c3, acc2[mi][ni][i][1]);
                float4 o;
                o.x = alpha * c0;
                o.y = alpha * c1;
                o.z = alpha * c2;
                o.w = alpha * c3;
                if (bias) {
                    o.x += bias[cb + 0];
                    o.y += bias[cb + 1];
                    o.z += bias[cb + 2];
                    o.w += bias[cb + 3];
                }
                *reinterpret_cast<float4*>(crow + cb) = o;
            }
        }
}

template <bool TRANSB, int MB, int NB>
static void run_gemm(int M, int N, int K,
                     const float* A, int lda, size_t sA,
                     const float* B, int ldb, size_t sB,
                     float* C, int ldc, size_t sC,
                     float alpha, const float* bias, int batch)
{
    dim3 grid(N / (64 * NB), M / (64 * MB), batch);
    gemm_kernel<TRANSB, MB, NB><<<grid, 256>>>(K, A, lda, sA, B, ldb, sB,
                                               C, ldc, sC, alpha, bias);
}

// ---------------- block reduction helpers (blockDim == 256) ----------------
__device__ __forceinline__ float warpMax(float v) {
#pragma unroll
    for (int o = 16; o; o >>= 1) v = fmaxf(v, __shfl_xor_sync(0xffffffffu, v, o));
    return v;
}
__device__ __forceinline__ float warpSum(float v) {
#pragma unroll
    for (int o = 16; o; o >>= 1) v += __shfl_xor_sync(0xffffffffu, v, o);
    return v;
}
__device__ __forceinline__ float blockMax(float v, float* red) {
    v = warpMax(v);
    if ((threadIdx.x & 31) == 0) red[threadIdx.x >> 5] = v;
    __syncthreads();
    float r = red[0];
#pragma unroll
    for (int i = 1; i < 8; i++) r = fmaxf(r, red[i]);
    __syncthreads();
    return r;
}
__device__ __forceinline__ float blockSum(float v, float* red) {
    v = warpSum(v);
    if ((threadIdx.x & 31) == 0) red[threadIdx.x >> 5] = v;
    __syncthreads();
    float r = red[0];
#pragma unroll
    for (int i = 1; i < 8; i++) r += red[i];
    __syncthreads();
    return r;
}

// =======================================================================================
// QKV split + L2-normalize. qkv row layout: [s*C + h*D + d], s in {q,k,v}.
// =======================================================================================
__global__ void qkv_split_kernel(const float* __restrict__ qkv,
                                 float* __restrict__ qn, float* __restrict__ kn,
                                 float* __restrict__ v,  float* __restrict__ vnf,
                                 float* __restrict__ enh)
{
    int w = (blockIdx.x * blockDim.x + threadIdx.x) >> 5;
    if (w >= N_ * H_) return;
    int lane = threadIdx.x & 31;
    int h = w & 3;
    int n = w >> 2;

    const float* src = qkv + (size_t)n * (3 * C_) + h * D_;
    float q0 = src[lane],            q1 = src[lane + 32];
    float k0 = src[C_ + lane],       k1 = src[C_ + lane + 32];
    float v0 = src[2 * C_ + lane],   v1 = src[2 * C_ + lane + 32];

    float sq = warpSum(q0 * q0 + q1 * q1);
    float sk = warpSum(k0 * k0 + k1 * k1);
    float sv = warpSum(v0 * v0 + v1 * v1);
    float iq = 1.f / fmaxf(sqrtf(sq), 1e-6f);
    float ik = 1.f / fmaxf(sqrtf(sk), 1e-6f);
    float iv = 1.f / fmaxf(sqrtf(sv), 1e-6f);

    size_t ho = ((size_t)h * N_ + n) * D_;
    qn[ho + lane] = q0 * iq;  qn[ho + lane + 32] = q1 * iq;
    kn[ho + lane] = k0 * ik;  kn[ho + lane + 32] = k1 * ik;
    v [ho + lane] = v0;       v [ho + lane + 32] = v1;

    size_t fo = (size_t)n * C_ + h * D_;
    vnf[fo + lane] = v0 * iv; vnf[fo + lane + 32] = v1 * iv;

    size_t eo = (size_t)n * (2 * C_) + C_ + h * D_;
    enh[eo + lane] = v0;      enh[eo + lane + 32] = v1;
}

// =======================================================================================
// Fused softmax + average (in place over logits_cls). One block per (h,n) row.
// =======================================================================================
__global__ void softmax_avg_kernel(float* __restrict__ lc_all,
                                   const float* __restrict__ lr_all,
                                   const float* __restrict__ scores)
{
    __shared__ float sc[N_];
    __shared__ float sr[N_];
    __shared__ float red[8];
    size_t base = (size_t)blockIdx.x * N_;
    float* lc = lc_all + base;
    const float* lr = lr_all + base;

    float mc = -3.4e38f, mr = -3.4e38f;
    for (int m = threadIdx.x; m < N_; m += 256) {
        float xc = lc[m] * (25.0f * scores[m]);
        float xr = lr[m] * 25.0f;
        sc[m] = xc; sr[m] = xr;
        mc = fmaxf(mc, xc); mr = fmaxf(mr, xr);
    }
    mc = blockMax(mc, red);
    mr = blockMax(mr, red);

    float tc = 0.f, tr = 0.f;
    for (int m = threadIdx.x; m < N_; m += 256) {
        float ec = expf(sc[m] - mc);
        float er = expf(sr[m] - mr);
        sc[m] = ec; sr[m] = er;
        tc += ec; tr += er;
    }
    tc = blockSum(tc, red);
    tr = blockSum(tr, red);

    float ic = 0.5f / tc, ir = 0.5f / tr;
    for (int m = threadIdx.x; m < N_; m += 256)
        lc[m] = sc[m] * ic + sr[m] * ir;
}

// =======================================================================================
// sim_round2 + obj_mask, one block per query row n.
// =======================================================================================
__global__ void sim_kernel(const float* __restrict__ attn,
                           const float* __restrict__ gcls,
                           const float* __restrict__ greg,
                           float* __restrict__ sr2,
                           float* __restrict__ obj)
{
    __shared__ float s[N_];
    __shared__ float red[8];
    int n = blockIdx.x;
    size_t ro = (size_t)n * N_;

    float mx = -3.4e38f;
    for (int m = threadIdx.x; m < N_; m += 256) {
        float v = 0.25f * (attn[ro + m] + attn[HS_ + ro + m] +
                           attn[2 * HS_ + ro + m] + attn[3 * HS_ + ro + m]);
        s[m] = v;
        mx = fmaxf(mx, v);
    }
    mx = blockMax(mx, red);

    float S = 0.f;
    for (int m = threadIdx.x; m < N_; m += 256) {
        float e  = expf(s[m] - mx);
        float me = (gcls[ro + m] > 0.75f) ? e : 0.f;
        s[m] = me;
        S += me;
    }
    S = blockSum(S, red);
    float invS = 1.f / S;

    float S2 = 0.f;
    for (int m = threadIdx.x; m < N_; m += 256) {
        float r = s[m] * invS;
        sr2[ro + m] = r;
        S2 += r;
    }
    S2 = blockSum(S2, red);
    float invS2 = 1.f / S2;

    for (int m = threadIdx.x; m < N_; m += 256)
        obj[ro + m] = (greg[ro + m] > 0.99f) ? s[m] * invS * invS2 : 0.f;
}

extern "C" void kernel_launch(void* const* d_in, const int* in_sizes, int n_in,
                              void* d_out, int out_size)
{
    (void)in_sizes; (void)n_in; (void)out_size;

    const float* cls_features = (const float*)d_in[0];
    const float* reg_features = (const float*)d_in[1];
    const float* cls_scores   = (const float*)d_in[2];
    const float* reg_proj_w   = (const float*)d_in[3];
    const float* qkv_cls_w    = (const float*)d_in[4];
    const float* qkv_reg_w    = (const float*)d_in[5];
    const float* l1_cls_w     = (const float*)d_in[6];
    const float* l1_cls_b     = (const float*)d_in[7];
    const float* l1_reg_w     = (const float*)d_in[8];
    const float* l1_reg_b     = (const float*)d_in[9];
    const float* l2_cls_w     = (const float*)d_in[10];
    const float* l2_cls_b     = (const float*)d_in[11];
    const float* l2_reg_w     = (const float*)d_in[12];
    const float* l2_reg_b     = (const float*)d_in[13];
    float* out = (float*)d_out;

    float *regp, *qkvc, *qkvr, *qnc, *knc, *vc, *qnr, *knr, *vr;
    float *vnfc, *vnfr, *bufA, *bufB, *sr2, *obj, *enhc, *enhr, *poolc, *poolr;
    cudaGetSymbolAddress((void**)&regp,  g_regp);
    cudaGetSymbolAddress((void**)&qkvc,  g_qkv_cls);
    cudaGetSymbolAddress((void**)&qkvr,  g_qkv_reg);
    cudaGetSymbolAddress((void**)&qnc,   g_qn_cls);
    cudaGetSymbolAddress((void**)&knc,   g_kn_cls);
    cudaGetSymbolAddress((void**)&vc,    g_v_cls);
    cudaGetSymbolAddress((void**)&qnr,   g_qn_reg);
    cudaGetSymbolAddress((void**)&knr,   g_kn_reg);
    cudaGetSymbolAddress((void**)&vr,    g_v_reg);
    cudaGetSymbolAddress((void**)&vnfc,  g_vnf_cls);
    cudaGetSymbolAddress((void**)&vnfr,  g_vnf_reg);
    cudaGetSymbolAddress((void**)&bufA,  g_bufA);
    cudaGetSymbolAddress((void**)&bufB,  g_bufB);
    cudaGetSymbolAddress((void**)&sr2,   g_sr2);
    cudaGetSymbolAddress((void**)&obj,   g_obj);
    cudaGetSymbolAddress((void**)&enhc,  g_enh_cls);
    cudaGetSymbolAddress((void**)&enhr,  g_enh_reg);
    cudaGetSymbolAddress((void**)&poolc, g_pool_cls);
    cudaGetSymbolAddress((void**)&poolr, g_pool_reg);

    // 1) reg branch 1x1 projection: [N,64] @ [256,64]^T -> [N,256]   (K=64)
    run_gemm<true, 1, 1>(N_, C_, D_, reg_features, D_, 0, reg_proj_w, D_, 0,
                         regp, C_, 0, 1.f, nullptr, 1);

    // 2) QKV projections: x @ W^T, W = [768,256]
    run_gemm<true, 2, 2>(N_, 3 * C_, C_, cls_features, C_, 0, qkv_cls_w, C_, 0,
                         qkvc, 3 * C_, 0, 1.f, nullptr, 1);
    run_gemm<true, 2, 2>(N_, 3 * C_, C_, regp, C_, 0, qkv_reg_w, C_, 0,
                         qkvr, 3 * C_, 0, 1.f, nullptr, 1);

    // 3) split + normalize (also writes v into 'ori' half of enh)
    qkv_split_kernel<<<(N_ * H_ * 32 + 255) / 256, 256>>>(qkvc, qnc, knc, vc, vnfc, enhc);
    qkv_split_kernel<<<(N_ * H_ * 32 + 255) / 256, 256>>>(qkvr, qnr, knr, vr, vnfr, enhr);

    // 4) attention logits per head: q @ k^T (batched over H)
    run_gemm<true, 2, 2>(N_, N_, D_, qnc, D_, QS_, knc, D_, QS_, bufA, N_, HS_, 1.f, nullptr, H_);
    run_gemm<true, 2, 2>(N_, N_, D_, qnr, D_, QS_, knr, D_, QS_, bufB, N_, HS_, 1.f, nullptr, H_);

    // 5) fused scale + dual softmax + average -> attn (in place in bufA)
    softmax_avg_kernel<<<H_ * N_, 256>>>(bufA, bufB, cls_scores);

    // 6) gram matrices (head-summed / H): vnf @ vnf^T * 0.25 (bufB reused)
    run_gemm<true, 2, 2>(N_, N_, C_, vnfc, C_, 0, vnfc, C_, 0, bufB, N_, 0, 0.25f, nullptr, 1);
    run_gemm<true, 2, 2>(N_, N_, C_, vnfr, C_, 0, vnfr, C_, 0, bufB + HS_, N_, 0, 0.25f, nullptr, 1);

    // 7) sim_round2 + obj_mask
    sim_kernel<<<N_, 256>>>(bufA, bufB, bufB + HS_, sr2, obj);

    // 8) inter = attn @ v per head, scattered into enh[:, 0:256] (sC = 64 per head)
    run_gemm<false, 1, 1>(N_, D_, N_, bufA, N_, HS_, vc, D_, QS_, enhc, 2 * C_, (size_t)D_, 1.f, nullptr, H_);
    run_gemm<false, 1, 1>(N_, D_, N_, bufA, N_, HS_, vr, D_, QS_, enhr, 2 * C_, (size_t)D_, 1.f, nullptr, H_);

    // 9) l1 linears: t = enh @ l1_w^T + b, written into pooled[:, 512:1024]
    run_gemm<true, 2, 1>(N_, 2 * C_, 2 * C_, enhc, 2 * C_, 0, l1_cls_w, 2 * C_, 0,
                         poolc + 2 * C_, 4 * C_, 0, 1.f, l1_cls_b, 1);
    run_gemm<true, 2, 1>(N_, 2 * C_, 2 * C_, enhr, 2 * C_, 0, l1_reg_w, 2 * C_, 0,
                         poolr + 2 * C_, 4 * C_, 0, 1.f, l1_reg_b, 1);

    // 10) pooled inter: mask @ t, written into pooled[:, 0:512]
    run_gemm<false, 2, 1>(N_, 2 * C_, N_, sr2, N_, 0, poolc + 2 * C_, 4 * C_, 0,
                          poolc, 4 * C_, 0, 1.f, nullptr, 1);
    run_gemm<false, 2, 1>(N_, 2 * C_, N_, obj, N_, 0, poolr + 2 * C_, 4 * C_, 0,
                          poolr, 4 * C_, 0, 1.f, nullptr, 1);

    // 11) l2 linears -> outputs (out_cls then out_reg)
    run_gemm<true, 2, 2>(N_, 4 * C_, 4 * C_, poolc, 4 * C_, 0, l2_cls_w, 4 * C_, 0,
                         out, 4 * C_, 0, 1.f, l2_cls_b, 1);
    run_gemm<true, 2, 2>(N_, 4 * C_, 4 * C_, poolr, 4 * C_, 0, l2_reg_w, 4 * C_, 0,
                         out + (size_t)N_ * 4 * C_, 4 * C_, 0, 1.f, l2_reg_b, 1);
}

// round 8
// speedup vs baseline: 1.4094x; 1.4094x over previous
#include <cuda_runtime.h>
#include <cstddef>

static constexpr int    N_  = 3072;
static constexpr int    C_  = 256;
static constexpr int    H_  = 4;
static constexpr int    D_  = 64;
static constexpr size_t HS_ = (size_t)N_ * N_;      // head stride in attn
static constexpr size_t QS_ = (size_t)N_ * D_;      // head stride in q/k/v

// ---------------- device scratch (module-load allocated, rule-compliant) ----------------
__device__ float g_regp   [N_ * C_];
__device__ float g_qkv_cls[N_ * 3 * C_];
__device__ float g_qkv_reg[N_ * 3 * C_];
__device__ float g_qn_cls [H_ * N_ * D_];
__device__ float g_kn_cls [H_ * N_ * D_];
__device__ float g_v_cls  [H_ * N_ * D_];
__device__ float g_qn_reg [H_ * N_ * D_];
__device__ float g_kn_reg [H_ * N_ * D_];
__device__ float g_v_reg  [H_ * N_ * D_];
__device__ float g_vnf_cls[N_ * C_];
__device__ float g_vnf_reg[N_ * C_];
__device__ float g_bufA[(size_t)H_ * N_ * N_];   // logits_cls -> averaged attn (in place)
__device__ float g_bufB[(size_t)H_ * N_ * N_];   // logits_reg -> later gram_cls | gram_reg
// sparse CSR-ish storage for sim_round2 / obj_mask (capacity N per row: never overflows)
__device__ float g_sr2v[(size_t)N_ * N_];
__device__ int   g_sr2i[(size_t)N_ * N_];
__device__ int   g_sr2c[N_];
__device__ float g_objv[(size_t)N_ * N_];
__device__ int   g_obji[(size_t)N_ * N_];
__device__ int   g_objc[N_];
__device__ float g_enh_cls[N_ * 2 * C_];
__device__ float g_enh_reg[N_ * 2 * C_];
__device__ float g_pool_cls[N_ * 4 * C_];
__device__ float g_pool_reg[N_ * 4 * C_];

// =======================================================================================
// Double-buffered, register-staged tiled SGEMM (scalar FFMA inner loop — proven fastest).
//   C[M,N] = alpha * A[M,K] x op(B) (+ bias[col])
//   TRANSB = true : B is [N,K] row-major (x @ W^T)
//   TRANSB = false: B is [K,N] row-major (NN)
// Tile: BM = 64*MB, BN = 64*NB, BK = 16; 256 threads; microtile (4*MB)x(4*NB).
// REQUIRES: M % BM == 0, N % BN == 0, K % BK == 0 (true for every call here).
// =======================================================================================
template <bool TRANSB, int MB, int NB>
__global__ __launch_bounds__(256)
void gemm_kernel(int K,
                 const float* __restrict__ A, int lda, size_t sA,
                 const float* __restrict__ B, int ldb, size_t sB,
                 float* __restrict__ C, int ldc, size_t sC,
                 float alpha, const float* __restrict__ bias)
{
    constexpr int BM = 64 * MB, BN = 64 * NB, BK = 16;
    __shared__ float As[2][BK][BM];
    __shared__ float Bs[2][BK][BN];

    const int bz = blockIdx.z;
    A += (size_t)bz * sA;
    B += (size_t)bz * sB;
    C += (size_t)bz * sC;

    const int m0  = blockIdx.y * BM;
    const int n0  = blockIdx.x * BN;
    const int tid = threadIdx.x;
    const int tx  = tid & 15;
    const int ty  = tid >> 4;

    int a_m[MB], a_k[MB];
    const float* aPtr[MB];
#pragma unroll
    for (int i = 0; i < MB; i++) {
        int id = tid + i * 256;
        a_m[i] = id >> 2;
        a_k[i] = (id & 3) << 2;
        aPtr[i] = A + (size_t)(m0 + a_m[i]) * lda + a_k[i];
    }

    int b_r[NB], b_c[NB];
    const float* bPtr[NB];
#pragma unroll
    for (int i = 0; i < NB; i++) {
        int id = tid + i * 256;
        if (TRANSB) {
            b_c[i] = id >> 2;
            b_r[i] = (id & 3) << 2;
            bPtr[i] = B + (size_t)(n0 + b_c[i]) * ldb + b_r[i];
        } else {
            b_r[i] = id / (16 * NB);
            b_c[i] = (id % (16 * NB)) << 2;
            bPtr[i] = B + (size_t)b_r[i] * ldb + n0 + b_c[i];
        }
    }

    float acc[MB][NB][4][4];
#pragma unroll
    for (int a = 0; a < MB; a++)
#pragma unroll
        for (int b = 0; b < NB; b++)
#pragma unroll
            for (int i = 0; i < 4; i++)
#pragma unroll
                for (int j = 0; j < 4; j++) acc[a][b][i][j] = 0.f;

    float4 avr[MB], bvr[NB];

#pragma unroll
    for (int i = 0; i < MB; i++) avr[i] = *reinterpret_cast<const float4*>(aPtr[i]);
#pragma unroll
    for (int i = 0; i < NB; i++) bvr[i] = *reinterpret_cast<const float4*>(bPtr[i]);

#pragma unroll
    for (int i = 0; i < MB; i++) {
        As[0][a_k[i] + 0][a_m[i]] = avr[i].x;
        As[0][a_k[i] + 1][a_m[i]] = avr[i].y;
        As[0][a_k[i] + 2][a_m[i]] = avr[i].z;
        As[0][a_k[i] + 3][a_m[i]] = avr[i].w;
    }
#pragma unroll
    for (int i = 0; i < NB; i++) {
        if (TRANSB) {
            Bs[0][b_r[i] + 0][b_c[i]] = bvr[i].x;
            Bs[0][b_r[i] + 1][b_c[i]] = bvr[i].y;
            Bs[0][b_r[i] + 2][b_c[i]] = bvr[i].z;
            Bs[0][b_r[i] + 3][b_c[i]] = bvr[i].w;
        } else {
            *reinterpret_cast<float4*>(&Bs[0][b_r[i]][b_c[i]]) = bvr[i];
        }
    }
    __syncthreads();

    int buf = 0;
    for (int k0 = 0; k0 < K; k0 += BK) {
        const bool has_next = (k0 + BK) < K;

        if (has_next) {
#pragma unroll
            for (int i = 0; i < MB; i++)
                avr[i] = *reinterpret_cast<const float4*>(aPtr[i] + (k0 + BK));
            if (TRANSB) {
#pragma unroll
                for (int i = 0; i < NB; i++)
                    bvr[i] = *reinterpret_cast<const float4*>(bPtr[i] + (k0 + BK));
            } else {
#pragma unroll
                for (int i = 0; i < NB; i++)
                    bvr[i] = *reinterpret_cast<const float4*>(bPtr[i] + (size_t)(k0 + BK) * ldb);
            }
        }

#pragma unroll
        for (int kk = 0; kk < BK; kk++) {
            float a[MB][4], b[NB][4];
#pragma unroll
            for (int mi = 0; mi < MB; mi++)
                *reinterpret_cast<float4*>(a[mi]) =
                    *reinterpret_cast<const float4*>(&As[buf][kk][ty * 4 + mi * 64]);
#pragma unroll
            for (int ni = 0; ni < NB; ni++)
                *reinterpret_cast<float4*>(b[ni]) =
                    *reinterpret_cast<const float4*>(&Bs[buf][kk][tx * 4 + ni * 64]);
#pragma unroll
            for (int mi = 0; mi < MB; mi++)
#pragma unroll
                for (int ni = 0; ni < NB; ni++)
#pragma unroll
                    for (int i = 0; i < 4; i++)
#pragma unroll
                        for (int j = 0; j < 4; j++)
                            acc[mi][ni][i][j] += a[mi][i] * b[ni][j];
        }

        if (has_next) {
            int nb = buf ^ 1;
#pragma unroll
            for (int i = 0; i < MB; i++) {
                As[nb][a_k[i] + 0][a_m[i]] = avr[i].x;
                As[nb][a_k[i] + 1][a_m[i]] = avr[i].y;
                As[nb][a_k[i] + 2][a_m[i]] = avr[i].z;
                As[nb][a_k[i] + 3][a_m[i]] = avr[i].w;
            }
#pragma unroll
            for (int i = 0; i < NB; i++) {
                if (TRANSB) {
                    Bs[nb][b_r[i] + 0][b_c[i]] = bvr[i].x;
                    Bs[nb][b_r[i] + 1][b_c[i]] = bvr[i].y;
                    Bs[nb][b_r[i] + 2][b_c[i]] = bvr[i].z;
                    Bs[nb][b_r[i] + 3][b_c[i]] = bvr[i].w;
                } else {
                    *reinterpret_cast<float4*>(&Bs[nb][b_r[i]][b_c[i]]) = bvr[i];
                }
            }
            __syncthreads();
            buf = nb;
        }
    }

#pragma unroll
    for (int mi = 0; mi < MB; mi++)
#pragma unroll
        for (int i = 0; i < 4; i++) {
            int r = m0 + mi * 64 + ty * 4 + i;
            float* crow = C + (size_t)r * ldc;
#pragma unroll
            for (int ni = 0; ni < NB; ni++) {
                int cb = n0 + ni * 64 + tx * 4;
                float4 o;
                o.x = alpha * acc[mi][ni][i][0];
                o.y = alpha * acc[mi][ni][i][1];
                o.z = alpha * acc[mi][ni][i][2];
                o.w = alpha * acc[mi][ni][i][3];
                if (bias) {
                    o.x += bias[cb + 0];
                    o.y += bias[cb + 1];
                    o.z += bias[cb + 2];
                    o.w += bias[cb + 3];
                }
                *reinterpret_cast<float4*>(crow + cb) = o;
            }
        }
}

template <bool TRANSB, int MB, int NB>
static void run_gemm(int M, int N, int K,
                     const float* A, int lda, size_t sA,
                     const float* B, int ldb, size_t sB,
                     float* C, int ldc, size_t sC,
                     float alpha, const float* bias, int batch)
{
    dim3 grid(N / (64 * NB), M / (64 * MB), batch);
    gemm_kernel<TRANSB, MB, NB><<<grid, 256>>>(K, A, lda, sA, B, ldb, sB,
                                               C, ldc, sC, alpha, bias);
}

// ---------------- block reduction helpers (blockDim == 256) ----------------
__device__ __forceinline__ float warpMax(float v) {
#pragma unroll
    for (int o = 16; o; o >>= 1) v = fmaxf(v, __shfl_xor_sync(0xffffffffu, v, o));
    return v;
}
__device__ __forceinline__ float warpSum(float v) {
#pragma unroll
    for (int o = 16; o; o >>= 1) v += __shfl_xor_sync(0xffffffffu, v, o);
    return v;
}
__device__ __forceinline__ float blockMax(float v, float* red) {
    v = warpMax(v);
    if ((threadIdx.x & 31) == 0) red[threadIdx.x >> 5] = v;
    __syncthreads();
    float r = red[0];
#pragma unroll
    for (int i = 1; i < 8; i++) r = fmaxf(r, red[i]);
    __syncthreads();
    return r;
}
__device__ __forceinline__ float blockSum(float v, float* red) {
    v = warpSum(v);
    if ((threadIdx.x & 31) == 0) red[threadIdx.x >> 5] = v;
    __syncthreads();
    float r = red[0];
#pragma unroll
    for (int i = 1; i < 8; i++) r += red[i];
    __syncthreads();
    return r;
}

// =======================================================================================
// QKV split + L2-normalize. qkv row layout: [s*C + h*D + d], s in {q,k,v}.
// =======================================================================================
__global__ void qkv_split_kernel(const float* __restrict__ qkv,
                                 float* __restrict__ qn, float* __restrict__ kn,
                                 float* __restrict__ v,  float* __restrict__ vnf,
                                 float* __restrict__ enh)
{
    int w = (blockIdx.x * blockDim.x + threadIdx.x) >> 5;
    if (w >= N_ * H_) return;
    int lane = threadIdx.x & 31;
    int h = w & 3;
    int n = w >> 2;

    const float* src = qkv + (size_t)n * (3 * C_) + h * D_;
    float q0 = src[lane],            q1 = src[lane + 32];
    float k0 = src[C_ + lane],       k1 = src[C_ + lane + 32];
    float v0 = src[2 * C_ + lane],   v1 = src[2 * C_ + lane + 32];

    float sq = warpSum(q0 * q0 + q1 * q1);
    float sk = warpSum(k0 * k0 + k1 * k1);
    float sv = warpSum(v0 * v0 + v1 * v1);
    float iq = 1.f / fmaxf(sqrtf(sq), 1e-6f);
    float ik = 1.f / fmaxf(sqrtf(sk), 1e-6f);
    float iv = 1.f / fmaxf(sqrtf(sv), 1e-6f);

    size_t ho = ((size_t)h * N_ + n) * D_;
    qn[ho + lane] = q0 * iq;  qn[ho + lane + 32] = q1 * iq;
    kn[ho + lane] = k0 * ik;  kn[ho + lane + 32] = k1 * ik;
    v [ho + lane] = v0;       v [ho + lane + 32] = v1;

    size_t fo = (size_t)n * C_ + h * D_;
    vnf[fo + lane] = v0 * iv; vnf[fo + lane + 32] = v1 * iv;

    size_t eo = (size_t)n * (2 * C_) + C_ + h * D_;
    enh[eo + lane] = v0;      enh[eo + lane + 32] = v1;
}

// =======================================================================================
// Fused softmax + average (in place over logits_cls). One block per (h,n) row.
// =======================================================================================
__global__ void softmax_avg_kernel(float* __restrict__ lc_all,
                                   const float* __restrict__ lr_all,
                                   const float* __restrict__ scores)
{
    __shared__ float sc[N_];
    __shared__ float sr[N_];
    __shared__ float red[8];
    size_t base = (size_t)blockIdx.x * N_;
    float* lc = lc_all + base;
    const float* lr = lr_all + base;

    float mc = -3.4e38f, mr = -3.4e38f;
    for (int m = threadIdx.x; m < N_; m += 256) {
        float xc = lc[m] * (25.0f * scores[m]);
        float xr = lr[m] * 25.0f;
        sc[m] = xc; sr[m] = xr;
        mc = fmaxf(mc, xc); mr = fmaxf(mr, xr);
    }
    mc = blockMax(mc, red);
    mr = blockMax(mr, red);

    float tc = 0.f, tr = 0.f;
    for (int m = threadIdx.x; m < N_; m += 256) {
        float ec = expf(sc[m] - mc);
        float er = expf(sr[m] - mr);
        sc[m] = ec; sr[m] = er;
        tc += ec; tr += er;
    }
    tc = blockSum(tc, red);
    tr = blockSum(tr, red);

    float ic = 0.5f / tc, ir = 0.5f / tr;
    for (int m = threadIdx.x; m < N_; m += 256)
        lc[m] = sc[m] * ic + sr[m] * ir;
}

// =======================================================================================
// sim_round2 + obj_mask — SPARSE output. One block (256 thr) per query row n.
//   s      = mean_h attn[h,n,:]
//   e      = exp(s - max); me = (gram_cls > 0.75) * e
//   sr2    = me / sum(me)                       -> CSR (idx,val,cnt), deterministic order
//   obj    = (gram_reg > 0.99) * sr2 / sum(sim_mask * sr2) -> CSR
// Compaction uses ballot-scan (no atomics) so the index order is ascending-m and
// identical on every run.
// =======================================================================================
__global__ void sim_kernel(const float* __restrict__ attn,
                           const float* __restrict__ gcls,
                           const float* __restrict__ greg,
                           int*  __restrict__ s_idx, float* __restrict__ s_val,
                           int*  __restrict__ s_cnt,
                           int*  __restrict__ o_idx, float* __restrict__ o_val,
                           int*  __restrict__ o_cnt)
{
    __shared__ float s[N_];
    __shared__ float red[8];
    __shared__ int wcS[8], wcO[8];
    int n = blockIdx.x;
    int tid = threadIdx.x;
    size_t ro = (size_t)n * N_;

    float mx = -3.4e38f;
    for (int m = tid; m < N_; m += 256) {
        float v = 0.25f * (attn[ro + m] + attn[HS_ + ro + m] +
                           attn[2 * HS_ + ro + m] + attn[3 * HS_ + ro + m]);
        s[m] = v;
        mx = fmaxf(mx, v);
    }
    mx = blockMax(mx, red);

    float S = 0.f;
    for (int m = tid; m < N_; m += 256) {
        float e  = expf(s[m] - mx);
        float me = (gcls[ro + m] > 0.75f) ? e : 0.f;
        s[m] = me;
        S += me;
    }
    S = blockSum(S, red);
    float invS = 1.f / S;

    float S2 = 0.f;
    for (int m = tid; m < N_; m += 256) S2 += s[m] * invS;
    S2 = blockSum(S2, red);
    float invS2 = 1.f / S2;

    // deterministic block compaction (ascending m)
    int baseS = 0, baseO = 0;
    int lane = tid & 31, wid = tid >> 5;
    unsigned lt = (lane == 0) ? 0u : (0xffffffffu >> (32 - lane));
    for (int m0 = 0; m0 < N_; m0 += 256) {
        int m = m0 + tid;
        float me = s[m];
        bool ps = (me > 0.f);
        bool po = ps && (greg[ro + m] > 0.99f);

        unsigned bs = __ballot_sync(0xffffffffu, ps);
        unsigned bo = __ballot_sync(0xffffffffu, po);
        if (lane == 0) { wcS[wid] = __popc(bs); wcO[wid] = __popc(bo); }
        __syncthreads();
        int offS = 0, offO = 0, totS = 0, totO = 0;
#pragma unroll
        for (int w = 0; w < 8; w++) {
            int cs = wcS[w], co = wcO[w];
            if (w < wid) { offS += cs; offO += co; }
            totS += cs; totO += co;
        }
        if (ps) {
            int p = baseS + offS + __popc(bs & lt);
            s_idx[ro + p] = m;
            s_val[ro + p] = me * invS;
        }
        if (po) {
            int p = baseO + offO + __popc(bo & lt);
            o_idx[ro + p] = m;
            o_val[ro + p] = me * invS * invS2;
        }
        baseS += totS; baseO += totO;
        __syncthreads();
    }
    if (tid == 0) { s_cnt[n] = baseS; o_cnt[n] = baseO; }
}

// =======================================================================================
// Sparse pooled mix: out row n (cols [0,512) of pool, ld=1024) =
//     sum_j val[n,j] * t[idx[n,j], :]   where t = pool cols [512,1024).
// Read/write column ranges are disjoint -> same buffer is safe.
// =======================================================================================
__global__ __launch_bounds__(128)
void pool_kernel(const int* __restrict__ idx, const float* __restrict__ val,
                 const int* __restrict__ cnt, float* __restrict__ pool)
{
    int n = blockIdx.x;
    int k = cnt[n];
    size_t ro = (size_t)n * N_;
    int c = threadIdx.x * 4;

    float4 acc = make_float4(0.f, 0.f, 0.f, 0.f);
    for (int j = 0; j < k; j++) {
        int   m = idx[ro + j];
        float w = val[ro + j];
        float4 tv = *reinterpret_cast<const float4*>(pool + (size_t)m * 1024 + 512 + c);
        acc.x += w * tv.x;
        acc.y += w * tv.y;
        acc.z += w * tv.z;
        acc.w += w * tv.w;
    }
    *reinterpret_cast<float4*>(pool + (size_t)n * 1024 + c) = acc;
}

extern "C" void kernel_launch(void* const* d_in, const int* in_sizes, int n_in,
                              void* d_out, int out_size)
{
    (void)in_sizes; (void)n_in; (void)out_size;

    const float* cls_features = (const float*)d_in[0];
    const float* reg_features = (const float*)d_in[1];
    const float* cls_scores   = (const float*)d_in[2];
    const float* reg_proj_w   = (const float*)d_in[3];
    const float* qkv_cls_w    = (const float*)d_in[4];
    const float* qkv_reg_w    = (const float*)d_in[5];
    const float* l1_cls_w     = (const float*)d_in[6];
    const float* l1_cls_b     = (const float*)d_in[7];
    const float* l1_reg_w     = (const float*)d_in[8];
    const float* l1_reg_b     = (const float*)d_in[9];
    const float* l2_cls_w     = (const float*)d_in[10];
    const float* l2_cls_b     = (const float*)d_in[11];
    const float* l2_reg_w     = (const float*)d_in[12];
    const float* l2_reg_b     = (const float*)d_in[13];
    float* out = (float*)d_out;

    float *regp, *qkvc, *qkvr, *qnc, *knc, *vc, *qnr, *knr, *vr;
    float *vnfc, *vnfr, *bufA, *bufB, *enhc, *enhr, *poolc, *poolr;
    float *sr2v, *objv;
    int *sr2i, *sr2c, *obji, *objc;
    cudaGetSymbolAddress((void**)&regp,  g_regp);
    cudaGetSymbolAddress((void**)&qkvc,  g_qkv_cls);
    cudaGetSymbolAddress((void**)&qkvr,  g_qkv_reg);
    cudaGetSymbolAddress((void**)&qnc,   g_qn_cls);
    cudaGetSymbolAddress((void**)&knc,   g_kn_cls);
    cudaGetSymbolAddress((void**)&vc,    g_v_cls);
    cudaGetSymbolAddress((void**)&qnr,   g_qn_reg);
    cudaGetSymbolAddress((void**)&knr,   g_kn_reg);
    cudaGetSymbolAddress((void**)&vr,    g_v_reg);
    cudaGetSymbolAddress((void**)&vnfc,  g_vnf_cls);
    cudaGetSymbolAddress((void**)&vnfr,  g_vnf_reg);
    cudaGetSymbolAddress((void**)&bufA,  g_bufA);
    cudaGetSymbolAddress((void**)&bufB,  g_bufB);
    cudaGetSymbolAddress((void**)&sr2v,  g_sr2v);
    cudaGetSymbolAddress((void**)&sr2i,  g_sr2i);
    cudaGetSymbolAddress((void**)&sr2c,  g_sr2c);
    cudaGetSymbolAddress((void**)&objv,  g_objv);
    cudaGetSymbolAddress((void**)&obji,  g_obji);
    cudaGetSymbolAddress((void**)&objc,  g_objc);
    cudaGetSymbolAddress((void**)&enhc,  g_enh_cls);
    cudaGetSymbolAddress((void**)&enhr,  g_enh_reg);
    cudaGetSymbolAddress((void**)&poolc, g_pool_cls);
    cudaGetSymbolAddress((void**)&poolr, g_pool_reg);

    // 1) reg branch 1x1 projection: [N,64] @ [256,64]^T -> [N,256]   (K=64)
    run_gemm<true, 1, 1>(N_, C_, D_, reg_features, D_, 0, reg_proj_w, D_, 0,
                         regp, C_, 0, 1.f, nullptr, 1);

    // 2) QKV projections: x @ W^T, W = [768,256]
    run_gemm<true, 2, 2>(N_, 3 * C_, C_, cls_features, C_, 0, qkv_cls_w, C_, 0,
                         qkvc, 3 * C_, 0, 1.f, nullptr, 1);
    run_gemm<true, 2, 2>(N_, 3 * C_, C_, regp, C_, 0, qkv_reg_w, C_, 0,
                         qkvr, 3 * C_, 0, 1.f, nullptr, 1);

    // 3) split + normalize (also writes v into 'ori' half of enh)
    qkv_split_kernel<<<(N_ * H_ * 32 + 255) / 256, 256>>>(qkvc, qnc, knc, vc, vnfc, enhc);
    qkv_split_kernel<<<(N_ * H_ * 32 + 255) / 256, 256>>>(qkvr, qnr, knr, vr, vnfr, enhr);

    // 4) attention logits per head: q @ k^T (batched over H)
    run_gemm<true, 2, 2>(N_, N_, D_, qnc, D_, QS_, knc, D_, QS_, bufA, N_, HS_, 1.f, nullptr, H_);
    run_gemm<true, 2, 2>(N_, N_, D_, qnr, D_, QS_, knr, D_, QS_, bufB, N_, HS_, 1.f, nullptr, H_);

    // 5) fused scale + dual softmax + average -> attn (in place in bufA)
    softmax_avg_kernel<<<H_ * N_, 256>>>(bufA, bufB, cls_scores);

    // 6) gram matrices (head-summed / H): vnf @ vnf^T * 0.25 (bufB reused)
    run_gemm<true, 2, 2>(N_, N_, C_, vnfc, C_, 0, vnfc, C_, 0, bufB, N_, 0, 0.25f, nullptr, 1);
    run_gemm<true, 2, 2>(N_, N_, C_, vnfr, C_, 0, vnfr, C_, 0, bufB + HS_, N_, 0, 0.25f, nullptr, 1);

    // 7) sim_round2 + obj_mask -> sparse CSR lists
    sim_kernel<<<N_, 256>>>(bufA, bufB, bufB + HS_,
                            sr2i, sr2v, sr2c, obji, objv, objc);

    // 8) inter = attn @ v per head, scattered into enh[:, 0:256] (sC = 64 per head)
    run_gemm<false, 1, 1>(N_, D_, N_, bufA, N_, HS_, vc, D_, QS_, enhc, 2 * C_, (size_t)D_, 1.f, nullptr, H_);
    run_gemm<false, 1, 1>(N_, D_, N_, bufA, N_, HS_, vr, D_, QS_, enhr, 2 * C_, (size_t)D_, 1.f, nullptr, H_);

    // 9) l1 linears: t = enh @ l1_w^T + b, written into pooled[:, 512:1024]
    run_gemm<true, 2, 1>(N_, 2 * C_, 2 * C_, enhc, 2 * C_, 0, l1_cls_w, 2 * C_, 0,
                         poolc + 2 * C_, 4 * C_, 0, 1.f, l1_cls_b, 1);
    run_gemm<true, 2, 1>(N_, 2 * C_, 2 * C_, enhr, 2 * C_, 0, l1_reg_w, 2 * C_, 0,
                         poolr + 2 * C_, 4 * C_, 0, 1.f, l1_reg_b, 1);

    // 10) pooled inter via sparse gather: pool[:, 0:512] = mask @ t
    pool_kernel<<<N_, 128>>>(sr2i, sr2v, sr2c, poolc);
    pool_kernel<<<N_, 128>>>(obji, objv, objc, poolr);

    // 11) l2 linears -> outputs (out_cls then out_reg)
    run_gemm<true, 2, 2>(N_, 4 * C_, 4 * C_, poolc, 4 * C_, 0, l2_cls_w, 4 * C_, 0,
                         out, 4 * C_, 0, 1.f, l2_cls_b, 1);
    run_gemm<true, 2, 2>(N_, 4 * C_, 4 * C_, poolr, 4 * C_, 0, l2_reg_w, 4 * C_, 0,
                         out + (size_t)N_ * 4 * C_, 4 * C_, 0, 1.f, l2_reg_b, 1);
}

// round 9
// speedup vs baseline: 1.5624x; 1.1085x over previous
#include <cuda_runtime.h>
#include <cstdint>
#include <cstddef>

static constexpr int    N_  = 3072;
static constexpr int    C_  = 256;
static constexpr int    H_  = 4;
static constexpr int    D_  = 64;
static constexpr size_t HS_ = (size_t)N_ * N_;
static constexpr size_t QS_ = (size_t)N_ * D_;

// ---------------- device scratch ----------------
__device__ float g_regp   [N_ * C_];
__device__ float g_qkv_cls[N_ * 3 * C_];
__device__ float g_qkv_reg[N_ * 3 * C_];
__device__ float g_qn_cls [H_ * N_ * D_];
__device__ float g_kn_cls [H_ * N_ * D_];
__device__ float g_v_cls  [H_ * N_ * D_];
__device__ float g_qn_reg [H_ * N_ * D_];
__device__ float g_kn_reg [H_ * N_ * D_];
__device__ float g_v_reg  [H_ * N_ * D_];
__device__ float g_vnf_cls[N_ * C_];
__device__ float g_vnf_reg[N_ * C_];
__device__ float g_bufA[(size_t)H_ * N_ * N_];
__device__ float g_bufB[(size_t)H_ * N_ * N_];
__device__ float g_sr2v[(size_t)N_ * N_];
__device__ int   g_sr2i[(size_t)N_ * N_];
__device__ int   g_sr2c[N_];
__device__ float g_objv[(size_t)N_ * N_];
__device__ int   g_obji[(size_t)N_ * N_];
__device__ int   g_objc[N_];
__device__ float g_enh_cls[N_ * 2 * C_];
__device__ float g_enh_reg[N_ * 2 * C_];
__device__ float g_pool_cls[N_ * 4 * C_];
__device__ float g_pool_reg[N_ * 4 * C_];

// ---------------- tensor-core primitives ----------------
__device__ __forceinline__ uint32_t cvta_shared(const void* p) {
    return (uint32_t)__cvta_generic_to_shared(p);
}
__device__ __forceinline__ void ldmatrix_x4(uint32_t& r0, uint32_t& r1,
                                            uint32_t& r2, uint32_t& r3, uint32_t addr) {
    asm volatile("ldmatrix.sync.aligned.m8n8.x4.shared.b16 {%0,%1,%2,%3}, [%4];"
                 : "=r"(r0), "=r"(r1), "=r"(r2), "=r"(r3) : "r"(addr));
}
__device__ __forceinline__ uint32_t f2tf32(float f) {
    uint32_t h;
    asm("cvt.rna.tf32.f32 %0, %1;" : "=r"(h) : "f"(f));
    return h;
}
__device__ __forceinline__ void mma_tf32(float* c, uint32_t a0, uint32_t a1,
                                         uint32_t a2, uint32_t a3,
                                         uint32_t b0, uint32_t b1) {
    asm volatile(
        "mma.sync.aligned.m16n8k8.row.col.f32.tf32.tf32.f32 "
        "{%0,%1,%2,%3}, {%4,%5,%6,%7}, {%8,%9}, {%0,%1,%2,%3};"
        : "+f"(c[0]), "+f"(c[1]), "+f"(c[2]), "+f"(c[3])
        : "r"(a0), "r"(a1), "r"(a2), "r"(a3), "r"(b0), "r"(b1));
}

// =======================================================================================
// 3xTF32 tensor-core GEMM.  C[M,N] = alpha * A[M,K] x op(B) (+ bias[col])
//   TRANSB = true : B is [N,K] row-major;  false: B is [K,N] row-major.
// Block 128 x BN (BN in {64,128}), BK=16, 256 threads (8 warps).
// smem layout k-contiguous with +4 skew so ldmatrix.x4.b16 yields tf32 fragments directly.
// REQUIRES: M%128==0, N%BN==0, K%16==0.
// =======================================================================================
template <bool TRANSB, int BN>
__global__ __launch_bounds__(256, 1)
void gemm_tc(int K,
             const float* __restrict__ A, int lda, size_t sA,
             const float* __restrict__ B, int ldb, size_t sB,
             float* __restrict__ C, int ldc, size_t sC,
             float alpha, const float* __restrict__ bias)
{
    constexpr int BM = 128, BK = 16, LDS = 20;           // 20 floats/row (skew 4)
    constexpr int WM  = (BN == 128) ? 2 : 4;             // warps along M
    constexpr int WN  = 8 / WM;                          // warps along N
    constexpr int WTM = BM / WM;                         // 64 or 32
    constexpr int MI  = WTM / 16;                        // m-atoms per warp (4 or 2)
    constexpr int NI  = 4;                               // n-atoms per warp (32/8)
    constexpr int BCH = BN / 64;                         // B copy chunks

    __shared__ __align__(16) float As[2][BM][LDS];
    __shared__ __align__(16) float Bs[2][BN][LDS];
    constexpr int ASTAGE = BM * LDS * 4;                 // bytes per A stage
    constexpr int BSTAGE = BN * LDS * 4;

    const int bz = blockIdx.z;
    A += (size_t)bz * sA;
    B += (size_t)bz * sB;
    C += (size_t)bz * sC;

    const int m0   = blockIdx.y * BM;
    const int n0   = blockIdx.x * BN;
    const int tid  = threadIdx.x;
    const int lane = tid & 31;
    const int wid  = tid >> 5;
    const int warpN = wid % WN;
    const int warpM = wid / WN;

    // ---- gmem copy coordinates ----
    int am[2], ak[2];
    const float* aPtr[2];
#pragma unroll
    for (int i = 0; i < 2; i++) {
        int id = tid + i * 256;
        am[i] = id >> 2;
        ak[i] = (id & 3) << 2;
        aPtr[i] = A + (size_t)(m0 + am[i]) * lda + ak[i];
    }
    int bn[BCH], bk[BCH];
    const float* bPtr[BCH];
#pragma unroll
    for (int i = 0; i < BCH; i++) {
        int id = tid + i * 256;
        if (TRANSB) {
            bn[i] = id >> 2;
            bk[i] = (id & 3) << 2;
            bPtr[i] = B + (size_t)(n0 + bn[i]) * ldb + bk[i];
        } else {
            bk[i] = id / (BN / 4);
            bn[i] = (id % (BN / 4)) << 2;
            bPtr[i] = B + (size_t)bk[i] * ldb + n0 + bn[i];
        }
    }

    // ---- ldmatrix per-lane base addresses (buf 0, k8-step 0) ----
    const int tt = lane >> 3, r8 = lane & 7;
    uint32_t addrA0[MI], addrB0[2];
#pragma unroll
    for (int mi = 0; mi < MI; mi++) {
        int row = warpM * WTM + mi * 16 + r8 + (tt & 1) * 8;
        addrA0[mi] = cvta_shared(&As[0][0][0]) + row * (LDS * 4) + (tt >> 1) * 16;
    }
#pragma unroll
    for (int p = 0; p < 2; p++) {
        int row = warpN * 32 + p * 16 + r8 + (tt & 1) * 8;
        addrB0[p] = cvta_shared(&Bs[0][0][0]) + row * (LDS * 4) + (tt >> 1) * 16;
    }

    float acc[MI][NI][4];
#pragma unroll
    for (int mi = 0; mi < MI; mi++)
#pragma unroll
        for (int ni = 0; ni < NI; ni++)
#pragma unroll
            for (int j = 0; j < 4; j++) acc[mi][ni][j] = 0.f;

    // ---- prologue: stage 0 ----
    float4 avr[2], bvr[BCH];
#pragma unroll
    for (int i = 0; i < 2; i++) avr[i] = *reinterpret_cast<const float4*>(aPtr[i]);
#pragma unroll
    for (int i = 0; i < BCH; i++) bvr[i] = *reinterpret_cast<const float4*>(bPtr[i]);

#pragma unroll
    for (int i = 0; i < 2; i++)
        *reinterpret_cast<float4*>(&As[0][am[i]][ak[i]]) = avr[i];
#pragma unroll
    for (int i = 0; i < BCH; i++) {
        if (TRANSB) {
            *reinterpret_cast<float4*>(&Bs[0][bn[i]][bk[i]]) = bvr[i];
        } else {
            Bs[0][bn[i] + 0][bk[i]] = bvr[i].x;
            Bs[0][bn[i] + 1][bk[i]] = bvr[i].y;
            Bs[0][bn[i] + 2][bk[i]] = bvr[i].z;
            Bs[0][bn[i] + 3][bk[i]] = bvr[i].w;
        }
    }
    __syncthreads();

    int buf = 0;
    for (int k0 = 0; k0 < K; k0 += BK) {
        const bool has_next = (k0 + BK) < K;
        if (has_next) {
#pragma unroll
            for (int i = 0; i < 2; i++)
                avr[i] = *reinterpret_cast<const float4*>(aPtr[i] + (k0 + BK));
            if (TRANSB) {
#pragma unroll
                for (int i = 0; i < BCH; i++)
                    bvr[i] = *reinterpret_cast<const float4*>(bPtr[i] + (k0 + BK));
            } else {
#pragma unroll
                for (int i = 0; i < BCH; i++)
                    bvr[i] = *reinterpret_cast<const float4*>(bPtr[i] + (size_t)(k0 + BK) * ldb);
            }
        }

        // ---- compute: two k8 steps ----
#pragma unroll
        for (int ks = 0; ks < 2; ks++) {
            const uint32_t off = (uint32_t)buf * ASTAGE + ks * 32;
            const uint32_t offB = (uint32_t)buf * BSTAGE + ks * 32;

            uint32_t aH[MI][4], aL[MI][4];
#pragma unroll
            for (int mi = 0; mi < MI; mi++) {
                uint32_t t0, t1, t2, t3;
                ldmatrix_x4(t0, t1, t2, t3, addrA0[mi] + off);
                uint32_t raw[4] = {t0, t1, t2, t3};
#pragma unroll
                for (int j = 0; j < 4; j++) {
                    float f = __uint_as_float(raw[j]);
                    uint32_t h = f2tf32(f);
                    aH[mi][j] = h;
                    aL[mi][j] = __float_as_uint(f - __uint_as_float(h));
                }
            }
            uint32_t bH[NI][2], bL[NI][2];
#pragma unroll
            for (int p = 0; p < 2; p++) {
                uint32_t r0, r1, r2, r3;
                ldmatrix_x4(r0, r1, r2, r3, addrB0[p] + offB);
                // atom 2p: (r0, r2); atom 2p+1: (r1, r3)
                uint32_t raw[2][2] = {{r0, r2}, {r1, r3}};
#pragma unroll
                for (int a = 0; a < 2; a++)
#pragma unroll
                    for (int j = 0; j < 2; j++) {
                        float f = __uint_as_float(raw[a][j]);
                        uint32_t h = f2tf32(f);
                        bH[2 * p + a][j] = h;
                        bL[2 * p + a][j] = __float_as_uint(f - __uint_as_float(h));
                    }
            }
#pragma unroll
            for (int mi = 0; mi < MI; mi++)
#pragma unroll
                for (int ni = 0; ni < NI; ni++) {
                    mma_tf32(acc[mi][ni], aH[mi][0], aH[mi][1], aH[mi][2], aH[mi][3],
                             bH[ni][0], bH[ni][1]);
                    mma_tf32(acc[mi][ni], aH[mi][0], aH[mi][1], aH[mi][2], aH[mi][3],
                             bL[ni][0], bL[ni][1]);
                    mma_tf32(acc[mi][ni], aL[mi][0], aL[mi][1], aL[mi][2], aL[mi][3],
                             bH[ni][0], bH[ni][1]);
                }
        }

        if (has_next) {
            int nb = buf ^ 1;
#pragma unroll
            for (int i = 0; i < 2; i++)
                *reinterpret_cast<float4*>(&As[nb][am[i]][ak[i]]) = avr[i];
#pragma unroll
            for (int i = 0; i < BCH; i++) {
                if (TRANSB) {
                    *reinterpret_cast<float4*>(&Bs[nb][bn[i]][bk[i]]) = bvr[i];
                } else {
                    Bs[nb][bn[i] + 0][bk[i]] = bvr[i].x;
                    Bs[nb][bn[i] + 1][bk[i]] = bvr[i].y;
                    Bs[nb][bn[i] + 2][bk[i]] = bvr[i].z;
                    Bs[nb][bn[i] + 3][bk[i]] = bvr[i].w;
                }
            }
            __syncthreads();
            buf = nb;
        }
    }

    // ---- epilogue: D layout m16n8: rows g, g+8; cols 2t, 2t+1 ----
    const int g = lane >> 2, t = lane & 3;
#pragma unroll
    for (int mi = 0; mi < MI; mi++) {
#pragma unroll
        for (int ni = 0; ni < NI; ni++) {
            int col = n0 + warpN * 32 + ni * 8 + t * 2;
            int r0  = m0 + warpM * WTM + mi * 16 + g;
            float2 o0, o1;
            o0.x = alpha * acc[mi][ni][0];
            o0.y = alpha * acc[mi][ni][1];
            o1.x = alpha * acc[mi][ni][2];
            o1.y = alpha * acc[mi][ni][3];
            if (bias) {
                float2 bv = *reinterpret_cast<const float2*>(bias + col);
                o0.x += bv.x; o0.y += bv.y;
                o1.x += bv.x; o1.y += bv.y;
            }
            *reinterpret_cast<float2*>(C + (size_t)r0 * ldc + col)       = o0;
            *reinterpret_cast<float2*>(C + (size_t)(r0 + 8) * ldc + col) = o1;
        }
    }
}

template <bool TRANSB, int BN>
static void run_gemm(int M, int N, int K,
                     const float* A, int lda, size_t sA,
                     const float* B, int ldb, size_t sB,
                     float* C, int ldc, size_t sC,
                     float alpha, const float* bias, int batch)
{
    dim3 grid(N / BN, M / 128, batch);
    gemm_tc<TRANSB, BN><<<grid, 256>>>(K, A, lda, sA, B, ldb, sB, C, ldc, sC, alpha, bias);
}

// ---------------- block reduction helpers ----------------
__device__ __forceinline__ float warpMax(float v) {
#pragma unroll
    for (int o = 16; o; o >>= 1) v = fmaxf(v, __shfl_xor_sync(0xffffffffu, v, o));
    return v;
}
__device__ __forceinline__ float warpSum(float v) {
#pragma unroll
    for (int o = 16; o; o >>= 1) v += __shfl_xor_sync(0xffffffffu, v, o);
    return v;
}
__device__ __forceinline__ float blockMax(float v, float* red) {
    v = warpMax(v);
    if ((threadIdx.x & 31) == 0) red[threadIdx.x >> 5] = v;
    __syncthreads();
    float r = red[0];
#pragma unroll
    for (int i = 1; i < 8; i++) r = fmaxf(r, red[i]);
    __syncthreads();
    return r;
}
__device__ __forceinline__ float blockSum(float v, float* red) {
    v = warpSum(v);
    if ((threadIdx.x & 31) == 0) red[threadIdx.x >> 5] = v;
    __syncthreads();
    float r = red[0];
#pragma unroll
    for (int i = 1; i < 8; i++) r += red[i];
    __syncthreads();
    return r;
}

// =======================================================================================
// QKV split + L2-normalize.
// =======================================================================================
__global__ void qkv_split_kernel(const float* __restrict__ qkv,
                                 float* __restrict__ qn, float* __restrict__ kn,
                                 float* __restrict__ v,  float* __restrict__ vnf,
                                 float* __restrict__ enh)
{
    int w = (blockIdx.x * blockDim.x + threadIdx.x) >> 5;
    if (w >= N_ * H_) return;
    int lane = threadIdx.x & 31;
    int h = w & 3;
    int n = w >> 2;

    const float* src = qkv + (size_t)n * (3 * C_) + h * D_;
    float q0 = src[lane],            q1 = src[lane + 32];
    float k0 = src[C_ + lane],       k1 = src[C_ + lane + 32];
    float v0 = src[2 * C_ + lane],   v1 = src[2 * C_ + lane + 32];

    float sq = warpSum(q0 * q0 + q1 * q1);
    float sk = warpSum(k0 * k0 + k1 * k1);
    float sv = warpSum(v0 * v0 + v1 * v1);
    float iq = 1.f / fmaxf(sqrtf(sq), 1e-6f);
    float ik = 1.f / fmaxf(sqrtf(sk), 1e-6f);
    float iv = 1.f / fmaxf(sqrtf(sv), 1e-6f);

    size_t ho = ((size_t)h * N_ + n) * D_;
    qn[ho + lane] = q0 * iq;  qn[ho + lane + 32] = q1 * iq;
    kn[ho + lane] = k0 * ik;  kn[ho + lane + 32] = k1 * ik;
    v [ho + lane] = v0;       v [ho + lane + 32] = v1;

    size_t fo = (size_t)n * C_ + h * D_;
    vnf[fo + lane] = v0 * iv; vnf[fo + lane + 32] = v1 * iv;

    size_t eo = (size_t)n * (2 * C_) + C_ + h * D_;
    enh[eo + lane] = v0;      enh[eo + lane + 32] = v1;
}

// =======================================================================================
// Fused dual softmax + average (in place over logits_cls). One block per (h,n) row.
// =======================================================================================
__global__ void softmax_avg_kernel(float* __restrict__ lc_all,
                                   const float* __restrict__ lr_all,
                                   const float* __restrict__ scores)
{
    __shared__ float sc[N_];
    __shared__ float sr[N_];
    __shared__ float red[8];
    size_t base = (size_t)blockIdx.x * N_;
    float* lc = lc_all + base;
    const float* lr = lr_all + base;

    float mc = -3.4e38f, mr = -3.4e38f;
    for (int m = threadIdx.x; m < N_; m += 256) {
        float xc = lc[m] * (25.0f * scores[m]);
        float xr = lr[m] * 25.0f;
        sc[m] = xc; sr[m] = xr;
        mc = fmaxf(mc, xc); mr = fmaxf(mr, xr);
    }
    mc = blockMax(mc, red);
    mr = blockMax(mr, red);

    float tc = 0.f, tr = 0.f;
    for (int m = threadIdx.x; m < N_; m += 256) {
        float ec = expf(sc[m] - mc);
        float er = expf(sr[m] - mr);
        sc[m] = ec; sr[m] = er;
        tc += ec; tr += er;
    }
    tc = blockSum(tc, red);
    tr = blockSum(tr, red);

    float ic = 0.5f / tc, ir = 0.5f / tr;
    for (int m = threadIdx.x; m < N_; m += 256)
        lc[m] = sc[m] * ic + sr[m] * ir;
}

// =======================================================================================
// sim_round2 + obj_mask -> sparse CSR lists (deterministic ballot-scan compaction).
// =======================================================================================
__global__ void sim_kernel(const float* __restrict__ attn,
                           const float* __restrict__ gcls,
                           const float* __restrict__ greg,
                           int*  __restrict__ s_idx, float* __restrict__ s_val,
                           int*  __restrict__ s_cnt,
                           int*  __restrict__ o_idx, float* __restrict__ o_val,
                           int*  __restrict__ o_cnt)
{
    __shared__ float s[N_];
    __shared__ float red[8];
    __shared__ int wcS[8], wcO[8];
    int n = blockIdx.x;
    int tid = threadIdx.x;
    size_t ro = (size_t)n * N_;

    float mx = -3.4e38f;
    for (int m = tid; m < N_; m += 256) {
        float v = 0.25f * (attn[ro + m] + attn[HS_ + ro + m] +
                           attn[2 * HS_ + ro + m] + attn[3 * HS_ + ro + m]);
        s[m] = v;
        mx = fmaxf(mx, v);
    }
    mx = blockMax(mx, red);

    float S = 0.f;
    for (int m = tid; m < N_; m += 256) {
        float e  = expf(s[m] - mx);
        float me = (gcls[ro + m] > 0.75f) ? e : 0.f;
        s[m] = me;
        S += me;
    }
    S = blockSum(S, red);
    float invS = 1.f / S;

    float S2 = 0.f;
    for (int m = tid; m < N_; m += 256) S2 += s[m] * invS;
    S2 = blockSum(S2, red);
    float invS2 = 1.f / S2;

    int baseS = 0, baseO = 0;
    int lane = tid & 31, wid = tid >> 5;
    unsigned lt = (lane == 0) ? 0u : (0xffffffffu >> (32 - lane));
    for (int m0 = 0; m0 < N_; m0 += 256) {
        int m = m0 + tid;
        float me = s[m];
        bool ps = (me > 0.f);
        bool po = ps && (greg[ro + m] > 0.99f);

        unsigned bs = __ballot_sync(0xffffffffu, ps);
        unsigned bo = __ballot_sync(0xffffffffu, po);
        if (lane == 0) { wcS[wid] = __popc(bs); wcO[wid] = __popc(bo); }
        __syncthreads();
        int offS = 0, offO = 0, totS = 0, totO = 0;
#pragma unroll
        for (int w = 0; w < 8; w++) {
            int cs = wcS[w], co = wcO[w];
            if (w < wid) { offS += cs; offO += co; }
            totS += cs; totO += co;
        }
        if (ps) {
            int p = baseS + offS + __popc(bs & lt);
            s_idx[ro + p] = m;
            s_val[ro + p] = me * invS;
        }
        if (po) {
            int p = baseO + offO + __popc(bo & lt);
            o_idx[ro + p] = m;
            o_val[ro + p] = me * invS * invS2;
        }
        baseS += totS; baseO += totO;
        __syncthreads();
    }
    if (tid == 0) { s_cnt[n] = baseS; o_cnt[n] = baseO; }
}

// =======================================================================================
// Sparse pooled mix: pool[n, 0:512] = sum_j val[n,j] * pool[idx[n,j], 512:1024].
// =======================================================================================
__global__ __launch_bounds__(128)
void pool_kernel(const int* __restrict__ idx, const float* __restrict__ val,
                 const int* __restrict__ cnt, float* __restrict__ pool)
{
    int n = blockIdx.x;
    int k = cnt[n];
    size_t ro = (size_t)n * N_;
    int c = threadIdx.x * 4;

    float4 acc = make_float4(0.f, 0.f, 0.f, 0.f);
    for (int j = 0; j < k; j++) {
        int   m = idx[ro + j];
        float w = val[ro + j];
        float4 tv = *reinterpret_cast<const float4*>(pool + (size_t)m * 1024 + 512 + c);
        acc.x += w * tv.x;
        acc.y += w * tv.y;
        acc.z += w * tv.z;
        acc.w += w * tv.w;
    }
    *reinterpret_cast<float4*>(pool + (size_t)n * 1024 + c) = acc;
}

extern "C" void kernel_launch(void* const* d_in, const int* in_sizes, int n_in,
                              void* d_out, int out_size)
{
    (void)in_sizes; (void)n_in; (void)out_size;

    const float* cls_features = (const float*)d_in[0];
    const float* reg_features = (const float*)d_in[1];
    const float* cls_scores   = (const float*)d_in[2];
    const float* reg_proj_w   = (const float*)d_in[3];
    const float* qkv_cls_w    = (const float*)d_in[4];
    const float* qkv_reg_w    = (const float*)d_in[5];
    const float* l1_cls_w     = (const float*)d_in[6];
    const float* l1_cls_b     = (const float*)d_in[7];
    const float* l1_reg_w     = (const float*)d_in[8];
    const float* l1_reg_b     = (const float*)d_in[9];
    const float* l2_cls_w     = (const float*)d_in[10];
    const float* l2_cls_b     = (const float*)d_in[11];
    const float* l2_reg_w     = (const float*)d_in[12];
    const float* l2_reg_b     = (const float*)d_in[13];
    float* out = (float*)d_out;

    float *regp, *qkvc, *qkvr, *qnc, *knc, *vc, *qnr, *knr, *vr;
    float *vnfc, *vnfr, *bufA, *bufB, *enhc, *enhr, *poolc, *poolr;
    float *sr2v, *objv;
    int *sr2i, *sr2c, *obji, *objc;
    cudaGetSymbolAddress((void**)&regp,  g_regp);
    cudaGetSymbolAddress((void**)&qkvc,  g_qkv_cls);
    cudaGetSymbolAddress((void**)&qkvr,  g_qkv_reg);
    cudaGetSymbolAddress((void**)&qnc,   g_qn_cls);
    cudaGetSymbolAddress((void**)&knc,   g_kn_cls);
    cudaGetSymbolAddress((void**)&vc,    g_v_cls);
    cudaGetSymbolAddress((void**)&qnr,   g_qn_reg);
    cudaGetSymbolAddress((void**)&knr,   g_kn_reg);
    cudaGetSymbolAddress((void**)&vr,    g_v_reg);
    cudaGetSymbolAddress((void**)&vnfc,  g_vnf_cls);
    cudaGetSymbolAddress((void**)&vnfr,  g_vnf_reg);
    cudaGetSymbolAddress((void**)&bufA,  g_bufA);
    cudaGetSymbolAddress((void**)&bufB,  g_bufB);
    cudaGetSymbolAddress((void**)&sr2v,  g_sr2v);
    cudaGetSymbolAddress((void**)&sr2i,  g_sr2i);
    cudaGetSymbolAddress((void**)&sr2c,  g_sr2c);
    cudaGetSymbolAddress((void**)&objv,  g_objv);
    cudaGetSymbolAddress((void**)&obji,  g_obji);
    cudaGetSymbolAddress((void**)&objc,  g_objc);
    cudaGetSymbolAddress((void**)&enhc,  g_enh_cls);
    cudaGetSymbolAddress((void**)&enhr,  g_enh_reg);
    cudaGetSymbolAddress((void**)&poolc, g_pool_cls);
    cudaGetSymbolAddress((void**)&poolr, g_pool_reg);

    // 1) reg branch 1x1 projection: [N,64] @ [256,64]^T -> [N,256]
    run_gemm<true, 128>(N_, C_, D_, reg_features, D_, 0, reg_proj_w, D_, 0,
                        regp, C_, 0, 1.f, nullptr, 1);

    // 2) QKV projections
    run_gemm<true, 128>(N_, 3 * C_, C_, cls_features, C_, 0, qkv_cls_w, C_, 0,
                        qkvc, 3 * C_, 0, 1.f, nullptr, 1);
    run_gemm<true, 128>(N_, 3 * C_, C_, regp, C_, 0, qkv_reg_w, C_, 0,
                        qkvr, 3 * C_, 0, 1.f, nullptr, 1);

    // 3) split + normalize
    qkv_split_kernel<<<(N_ * H_ * 32 + 255) / 256, 256>>>(qkvc, qnc, knc, vc, vnfc, enhc);
    qkv_split_kernel<<<(N_ * H_ * 32 + 255) / 256, 256>>>(qkvr, qnr, knr, vr, vnfr, enhr);

    // 4) attention logits per head
    run_gemm<true, 128>(N_, N_, D_, qnc, D_, QS_, knc, D_, QS_, bufA, N_, HS_, 1.f, nullptr, H_);
    run_gemm<true, 128>(N_, N_, D_, qnr, D_, QS_, knr, D_, QS_, bufB, N_, HS_, 1.f, nullptr, H_);

    // 5) fused dual softmax + average
    softmax_avg_kernel<<<H_ * N_, 256>>>(bufA, bufB, cls_scores);

    // 6) gram matrices (x0.25)
    run_gemm<true, 128>(N_, N_, C_, vnfc, C_, 0, vnfc, C_, 0, bufB, N_, 0, 0.25f, nullptr, 1);
    run_gemm<true, 128>(N_, N_, C_, vnfr, C_, 0, vnfr, C_, 0, bufB + HS_, N_, 0, 0.25f, nullptr, 1);

    // 7) sim_round2 + obj_mask -> sparse
    sim_kernel<<<N_, 256>>>(bufA, bufB, bufB + HS_,
                            sr2i, sr2v, sr2c, obji, objv, objc);

    // 8) inter = attn @ v per head into enh[:, 0:256]
    run_gemm<false, 64>(N_, D_, N_, bufA, N_, HS_, vc, D_, QS_, enhc, 2 * C_, (size_t)D_, 1.f, nullptr, H_);
    run_gemm<false, 64>(N_, D_, N_, bufA, N_, HS_, vr, D_, QS_, enhr, 2 * C_, (size_t)D_, 1.f, nullptr, H_);

    // 9) l1 linears into pooled[:, 512:1024]
    run_gemm<true, 128>(N_, 2 * C_, 2 * C_, enhc, 2 * C_, 0, l1_cls_w, 2 * C_, 0,
                        poolc + 2 * C_, 4 * C_, 0, 1.f, l1_cls_b, 1);
    run_gemm<true, 128>(N_, 2 * C_, 2 * C_, enhr, 2 * C_, 0, l1_reg_w, 2 * C_, 0,
                        poolr + 2 * C_, 4 * C_, 0, 1.f, l1_reg_b, 1);

    // 10) pooled inter via sparse gather
    pool_kernel<<<N_, 128>>>(sr2i, sr2v, sr2c, poolc);
    pool_kernel<<<N_, 128>>>(obji, objv, objc, poolr);

    // 11) l2 linears -> outputs
    run_gemm<true, 128>(N_, 4 * C_, 4 * C_, poolc, 4 * C_, 0, l2_cls_w, 4 * C_, 0,
                        out, 4 * C_, 0, 1.f, l2_cls_b, 1);
    run_gemm<true, 128>(N_, 4 * C_, 4 * C_, poolr, 4 * C_, 0, l2_reg_w, 4 * C_, 0,
                        out + (size_t)N_ * 4 * C_, 4 * C_, 0, 1.f, l2_reg_b, 1);
}

// round 10
// speedup vs baseline: 1.8990x; 1.2154x over previous
#include <cuda_runtime.h>
#include <cuda_bf16.h>
#include <cstdint>
#include <cstddef>

static constexpr int    N_  = 3072;
static constexpr int    C_  = 256;
static constexpr int    H_  = 4;
static constexpr int    D_  = 64;
static constexpr size_t HS_ = (size_t)N_ * N_;
static constexpr size_t QS_ = (size_t)N_ * D_;

// ---------------- device scratch ----------------
__device__ float g_regp   [N_ * C_];
__device__ float g_qkv_cls[N_ * 3 * C_];
__device__ float g_qkv_reg[N_ * 3 * C_];
__device__ float g_qn_cls [H_ * N_ * D_];
__device__ float g_kn_cls [H_ * N_ * D_];
__device__ float g_v_cls  [H_ * N_ * D_];
__device__ float g_qn_reg [H_ * N_ * D_];
__device__ float g_kn_reg [H_ * N_ * D_];
__device__ float g_v_reg  [H_ * N_ * D_];
__device__ float g_vnf_cls[N_ * C_];
__device__ float g_vnf_reg[N_ * C_];
__device__ float g_bufA[(size_t)H_ * N_ * N_];
__device__ float g_bufB[(size_t)H_ * N_ * N_];
__device__ float g_sr2v[(size_t)N_ * N_];
__device__ int   g_sr2i[(size_t)N_ * N_];
__device__ int   g_sr2c[N_];
__device__ float g_objv[(size_t)N_ * N_];
__device__ int   g_obji[(size_t)N_ * N_];
__device__ int   g_objc[N_];
__device__ float g_enh_cls[N_ * 2 * C_];
__device__ float g_enh_reg[N_ * 2 * C_];
__device__ float g_pool_cls[N_ * 4 * C_];
__device__ float g_pool_reg[N_ * 4 * C_];

// ---------------- tensor-core primitives ----------------
__device__ __forceinline__ uint32_t cvta_shared(const void* p) {
    return (uint32_t)__cvta_generic_to_shared(p);
}
__device__ __forceinline__ void ldmatrix_x4(uint32_t& r0, uint32_t& r1,
                                            uint32_t& r2, uint32_t& r3, uint32_t addr) {
    asm volatile("ldmatrix.sync.aligned.m8n8.x4.shared.b16 {%0,%1,%2,%3}, [%4];"
                 : "=r"(r0), "=r"(r1), "=r"(r2), "=r"(r3) : "r"(addr));
}
__device__ __forceinline__ void mma_bf16(float* c, uint32_t a0, uint32_t a1,
                                         uint32_t a2, uint32_t a3,
                                         uint32_t b0, uint32_t b1) {
    asm volatile(
        "mma.sync.aligned.m16n8k16.row.col.f32.bf16.bf16.f32 "
        "{%0,%1,%2,%3}, {%4,%5,%6,%7}, {%8,%9}, {%0,%1,%2,%3};"
        : "+f"(c[0]), "+f"(c[1]), "+f"(c[2]), "+f"(c[3])
        : "r"(a0), "r"(a1), "r"(a2), "r"(a3), "r"(b0), "r"(b1));
}
// hi/lo bf16 split: x ~= hi + lo, residual ~2^-18 * |x|
__device__ __forceinline__ void split_bf16(float x, __nv_bfloat16& h, __nv_bfloat16& l) {
    h = __float2bfloat16_rn(x);
    l = __float2bfloat16_rn(x - __bfloat162float(h));
}

// =======================================================================================
// 3xBF16 tensor-core GEMM.  C[M,N] = alpha * A[M,K] x op(B) (+ bias[col])
//   TRANSB = true : B is [N,K] row-major;  false: B is [K,N] row-major.
// Block 128 x BN (BN in {64,128}), BK=16 (one k16 mma step per stage), 256 threads.
// smem holds bf16 hi/lo pairs, k-contiguous, 48-byte rows (LDB=24 bf16) so every
// ldmatrix 16B chunk is aligned and rows hit distinct bank groups.
// REQUIRES: M%128==0, N%BN==0, K%16==0.
// =======================================================================================
template <bool TRANSB, int BN>
__global__ __launch_bounds__(256, 1)
void gemm_tc(int K,
             const float* __restrict__ A, int lda, size_t sA,
             const float* __restrict__ B, int ldb, size_t sB,
             float* __restrict__ C, int ldc, size_t sC,
             float alpha, const float* __restrict__ bias)
{
    constexpr int BM = 128, BK = 16, LDB = 24;          // 24 bf16 = 48 B per row
    constexpr int WM  = (BN == 128) ? 2 : 4;
    constexpr int WN  = 8 / WM;
    constexpr int WTM = BM / WM;                        // 64 or 32
    constexpr int MI  = WTM / 16;                       // 4 or 2
    constexpr int NI  = 4;                              // 8/WN*... n atoms (32 cols/warp)
    constexpr int BCH = (BN * BK) / 1024;               // float4 copy chunks for B

    __shared__ __align__(16) __nv_bfloat16 AsH[2][BM][LDB];
    __shared__ __align__(16) __nv_bfloat16 AsL[2][BM][LDB];
    __shared__ __align__(16) __nv_bfloat16 BsH[2][BN][LDB];
    __shared__ __align__(16) __nv_bfloat16 BsL[2][BN][LDB];
    constexpr uint32_t ASTAGE = BM * LDB * 2;
    constexpr uint32_t BSTAGE = BN * LDB * 2;

    const int bz = blockIdx.z;
    A += (size_t)bz * sA;
    B += (size_t)bz * sB;
    C += (size_t)bz * sC;

    const int m0   = blockIdx.y * BM;
    const int n0   = blockIdx.x * BN;
    const int tid  = threadIdx.x;
    const int lane = tid & 31;
    const int wid  = tid >> 5;
    const int warpN = wid % WN;
    const int warpM = wid / WN;

    // ---- gmem copy coordinates (2 float4 chunks for A, BCH for B) ----
    int am[2], ak[2];
    const float* aPtr[2];
#pragma unroll
    for (int i = 0; i < 2; i++) {
        int id = tid + i * 256;
        am[i] = id >> 2;
        ak[i] = (id & 3) << 2;
        aPtr[i] = A + (size_t)(m0 + am[i]) * lda + ak[i];
    }
    int bn[2], bk[2];
    const float* bPtr[2];
#pragma unroll
    for (int i = 0; i < BCH; i++) {
        int id = tid + i * 256;
        if (TRANSB) {
            bn[i] = id >> 2;
            bk[i] = (id & 3) << 2;
            bPtr[i] = B + (size_t)(n0 + bn[i]) * ldb + bk[i];
        } else {
            bk[i] = id / (BN / 4);
            bn[i] = (id % (BN / 4)) << 2;
            bPtr[i] = B + (size_t)bk[i] * ldb + n0 + bn[i];
        }
    }

    // ---- smem store helpers ----
    auto storeA = [&](int buf, float4 v, int i) {
        __nv_bfloat16 h0, h1, h2, h3, l0, l1, l2, l3;
        split_bf16(v.x, h0, l0); split_bf16(v.y, h1, l1);
        split_bf16(v.z, h2, l2); split_bf16(v.w, h3, l3);
        __nv_bfloat162* ph = reinterpret_cast<__nv_bfloat162*>(&AsH[buf][am[i]][ak[i]]);
        __nv_bfloat162* pl = reinterpret_cast<__nv_bfloat162*>(&AsL[buf][am[i]][ak[i]]);
        ph[0] = __nv_bfloat162(h0, h1); ph[1] = __nv_bfloat162(h2, h3);
        pl[0] = __nv_bfloat162(l0, l1); pl[1] = __nv_bfloat162(l2, l3);
    };
    auto storeB = [&](int buf, float4 v, int i) {
        __nv_bfloat16 h0, h1, h2, h3, l0, l1, l2, l3;
        split_bf16(v.x, h0, l0); split_bf16(v.y, h1, l1);
        split_bf16(v.z, h2, l2); split_bf16(v.w, h3, l3);
        if (TRANSB) {
            __nv_bfloat162* ph = reinterpret_cast<__nv_bfloat162*>(&BsH[buf][bn[i]][bk[i]]);
            __nv_bfloat162* pl = reinterpret_cast<__nv_bfloat162*>(&BsL[buf][bn[i]][bk[i]]);
            ph[0] = __nv_bfloat162(h0, h1); ph[1] = __nv_bfloat162(h2, h3);
            pl[0] = __nv_bfloat162(l0, l1); pl[1] = __nv_bfloat162(l2, l3);
        } else {
            BsH[buf][bn[i] + 0][bk[i]] = h0; BsL[buf][bn[i] + 0][bk[i]] = l0;
            BsH[buf][bn[i] + 1][bk[i]] = h1; BsL[buf][bn[i] + 1][bk[i]] = l1;
            BsH[buf][bn[i] + 2][bk[i]] = h2; BsL[buf][bn[i] + 2][bk[i]] = l2;
            BsH[buf][bn[i] + 3][bk[i]] = h3; BsL[buf][bn[i] + 3][bk[i]] = l3;
        }
    };

    // ---- ldmatrix per-lane addresses (buf 0) ----
    // A: lanes 0-7 rows m0-7 chunk0, 8-15 rows m8-15 chunk0, 16-23 m0-7 chunk1, 24-31 m8-15 chunk1
    const int aRow = lane & 15, aChunk = lane >> 4;
    // B: lanes 0-7 n0-7 chunk0, 8-15 n0-7 chunk1, 16-23 n8-15 chunk0, 24-31 n8-15 chunk1
    const int bRow = ((lane >> 4) << 3) + (lane & 7), bChunk = (lane >> 3) & 1;
    uint32_t adrAH[MI], adrAL[MI], adrBH[2], adrBL[2];
#pragma unroll
    for (int mi = 0; mi < MI; mi++) {
        int row = warpM * WTM + mi * 16 + aRow;
        adrAH[mi] = cvta_shared(&AsH[0][0][0]) + row * 48 + aChunk * 16;
        adrAL[mi] = cvta_shared(&AsL[0][0][0]) + row * 48 + aChunk * 16;
    }
#pragma unroll
    for (int p = 0; p < 2; p++) {
        int row = warpN * 32 + p * 16 + bRow;
        adrBH[p] = cvta_shared(&BsH[0][0][0]) + row * 48 + bChunk * 16;
        adrBL[p] = cvta_shared(&BsL[0][0][0]) + row * 48 + bChunk * 16;
    }

    float acc[MI][NI][4];
#pragma unroll
    for (int mi = 0; mi < MI; mi++)
#pragma unroll
        for (int ni = 0; ni < NI; ni++)
#pragma unroll
            for (int j = 0; j < 4; j++) acc[mi][ni][j] = 0.f;

    // ---- prologue: stage 0 ----
    float4 avr[2], bvr[2];
#pragma unroll
    for (int i = 0; i < 2; i++) avr[i] = *reinterpret_cast<const float4*>(aPtr[i]);
#pragma unroll
    for (int i = 0; i < BCH; i++) bvr[i] = *reinterpret_cast<const float4*>(bPtr[i]);
#pragma unroll
    for (int i = 0; i < 2; i++) storeA(0, avr[i], i);
#pragma unroll
    for (int i = 0; i < BCH; i++) storeB(0, bvr[i], i);
    __syncthreads();

    int buf = 0;
    for (int k0 = 0; k0 < K; k0 += BK) {
        const bool has_next = (k0 + BK) < K;
        if (has_next) {
#pragma unroll
            for (int i = 0; i < 2; i++)
                avr[i] = *reinterpret_cast<const float4*>(aPtr[i] + (k0 + BK));
            if (TRANSB) {
#pragma unroll
                for (int i = 0; i < BCH; i++)
                    bvr[i] = *reinterpret_cast<const float4*>(bPtr[i] + (k0 + BK));
            } else {
#pragma unroll
                for (int i = 0; i < BCH; i++)
                    bvr[i] = *reinterpret_cast<const float4*>(bPtr[i] + (size_t)(k0 + BK) * ldb);
            }
        }

        // ---- compute one k16 step ----
        const uint32_t offA = (uint32_t)buf * ASTAGE;
        const uint32_t offB = (uint32_t)buf * BSTAGE;
        uint32_t aH[MI][4], aL[MI][4], bH[NI][2], bL[NI][2];
#pragma unroll
        for (int mi = 0; mi < MI; mi++) {
            ldmatrix_x4(aH[mi][0], aH[mi][1], aH[mi][2], aH[mi][3], adrAH[mi] + offA);
            ldmatrix_x4(aL[mi][0], aL[mi][1], aL[mi][2], aL[mi][3], adrAL[mi] + offA);
        }
#pragma unroll
        for (int p = 0; p < 2; p++) {
            uint32_t r0, r1, r2, r3;
            ldmatrix_x4(r0, r1, r2, r3, adrBH[p] + offB);
            bH[2 * p][0] = r0; bH[2 * p][1] = r1;
            bH[2 * p + 1][0] = r2; bH[2 * p + 1][1] = r3;
            ldmatrix_x4(r0, r1, r2, r3, adrBL[p] + offB);
            bL[2 * p][0] = r0; bL[2 * p][1] = r1;
            bL[2 * p + 1][0] = r2; bL[2 * p + 1][1] = r3;
        }
#pragma unroll
        for (int mi = 0; mi < MI; mi++)
#pragma unroll
            for (int ni = 0; ni < NI; ni++) {
                mma_bf16(acc[mi][ni], aH[mi][0], aH[mi][1], aH[mi][2], aH[mi][3],
                         bH[ni][0], bH[ni][1]);
                mma_bf16(acc[mi][ni], aH[mi][0], aH[mi][1], aH[mi][2], aH[mi][3],
                         bL[ni][0], bL[ni][1]);
                mma_bf16(acc[mi][ni], aL[mi][0], aL[mi][1], aL[mi][2], aL[mi][3],
                         bH[ni][0], bH[ni][1]);
            }

        if (has_next) {
            int nb = buf ^ 1;
#pragma unroll
            for (int i = 0; i < 2; i++) storeA(nb, avr[i], i);
#pragma unroll
            for (int i = 0; i < BCH; i++) storeB(nb, bvr[i], i);
            __syncthreads();
            buf = nb;
        }
    }

    // ---- epilogue: D m16n8 layout: rows g, g+8; cols 2t, 2t+1 ----
    const int g = lane >> 2, t = lane & 3;
#pragma unroll
    for (int mi = 0; mi < MI; mi++) {
#pragma unroll
        for (int ni = 0; ni < NI; ni++) {
            int col = n0 + warpN * 32 + ni * 8 + t * 2;
            int r0  = m0 + warpM * WTM + mi * 16 + g;
            float2 o0, o1;
            o0.x = alpha * acc[mi][ni][0];
            o0.y = alpha * acc[mi][ni][1];
            o1.x = alpha * acc[mi][ni][2];
            o1.y = alpha * acc[mi][ni][3];
            if (bias) {
                float2 bv = *reinterpret_cast<const float2*>(bias + col);
                o0.x += bv.x; o0.y += bv.y;
                o1.x += bv.x; o1.y += bv.y;
            }
            *reinterpret_cast<float2*>(C + (size_t)r0 * ldc + col)       = o0;
            *reinterpret_cast<float2*>(C + (size_t)(r0 + 8) * ldc + col) = o1;
        }
    }
}

template <bool TRANSB, int BN>
static void run_gemm(int M, int N, int K,
                     const float* A, int lda, size_t sA,
                     const float* B, int ldb, size_t sB,
                     float* C, int ldc, size_t sC,
                     float alpha, const float* bias, int batch)
{
    dim3 grid(N / BN, M / 128, batch);
    gemm_tc<TRANSB, BN><<<grid, 256>>>(K, A, lda, sA, B, ldb, sB, C, ldc, sC, alpha, bias);
}

// ---------------- block reduction helpers ----------------
__device__ __forceinline__ float warpMax(float v) {
#pragma unroll
    for (int o = 16; o; o >>= 1) v = fmaxf(v, __shfl_xor_sync(0xffffffffu, v, o));
    return v;
}
__device__ __forceinline__ float warpSum(float v) {
#pragma unroll
    for (int o = 16; o; o >>= 1) v += __shfl_xor_sync(0xffffffffu, v, o);
    return v;
}
__device__ __forceinline__ float blockMax(float v, float* red) {
    v = warpMax(v);
    if ((threadIdx.x & 31) == 0) red[threadIdx.x >> 5] = v;
    __syncthreads();
    float r = red[0];
#pragma unroll
    for (int i = 1; i < 8; i++) r = fmaxf(r, red[i]);
    __syncthreads();
    return r;
}
__device__ __forceinline__ float blockSum(float v, float* red) {
    v = warpSum(v);
    if ((threadIdx.x & 31) == 0) red[threadIdx.x >> 5] = v;
    __syncthreads();
    float r = red[0];
#pragma unroll
    for (int i = 1; i < 8; i++) r += red[i];
    __syncthreads();
    return r;
}

// =======================================================================================
// QKV split + L2-normalize.
// =======================================================================================
__global__ void qkv_split_kernel(const float* __restrict__ qkv,
                                 float* __restrict__ qn, float* __restrict__ kn,
                                 float* __restrict__ v,  float* __restrict__ vnf,
                                 float* __restrict__ enh)
{
    int w = (blockIdx.x * blockDim.x + threadIdx.x) >> 5;
    if (w >= N_ * H_) return;
    int lane = threadIdx.x & 31;
    int h = w & 3;
    int n = w >> 2;

    const float* src = qkv + (size_t)n * (3 * C_) + h * D_;
    float q0 = src[lane],            q1 = src[lane + 32];
    float k0 = src[C_ + lane],       k1 = src[C_ + lane + 32];
    float v0 = src[2 * C_ + lane],   v1 = src[2 * C_ + lane + 32];

    float sq = warpSum(q0 * q0 + q1 * q1);
    float sk = warpSum(k0 * k0 + k1 * k1);
    float sv = warpSum(v0 * v0 + v1 * v1);
    float iq = 1.f / fmaxf(sqrtf(sq), 1e-6f);
    float ik = 1.f / fmaxf(sqrtf(sk), 1e-6f);
    float iv = 1.f / fmaxf(sqrtf(sv), 1e-6f);

    size_t ho = ((size_t)h * N_ + n) * D_;
    qn[ho + lane] = q0 * iq;  qn[ho + lane + 32] = q1 * iq;
    kn[ho + lane] = k0 * ik;  kn[ho + lane + 32] = k1 * ik;
    v [ho + lane] = v0;       v [ho + lane + 32] = v1;

    size_t fo = (size_t)n * C_ + h * D_;
    vnf[fo + lane] = v0 * iv; vnf[fo + lane + 32] = v1 * iv;

    size_t eo = (size_t)n * (2 * C_) + C_ + h * D_;
    enh[eo + lane] = v0;      enh[eo + lane + 32] = v1;
}

// =======================================================================================
// Fused dual softmax + average (in place over logits_cls). One block per (h,n) row.
// =======================================================================================
__global__ void softmax_avg_kernel(float* __restrict__ lc_all,
                                   const float* __restrict__ lr_all,
                                   const float* __restrict__ scores)
{
    __shared__ float sc[N_];
    __shared__ float sr[N_];
    __shared__ float red[8];
    size_t base = (size_t)blockIdx.x * N_;
    float* lc = lc_all + base;
    const float* lr = lr_all + base;

    float mc = -3.4e38f, mr = -3.4e38f;
    for (int m = threadIdx.x; m < N_; m += 256) {
        float xc = lc[m] * (25.0f * scores[m]);
        float xr = lr[m] * 25.0f;
        sc[m] = xc; sr[m] = xr;
        mc = fmaxf(mc, xc); mr = fmaxf(mr, xr);
    }
    mc = blockMax(mc, red);
    mr = blockMax(mr, red);

    float tc = 0.f, tr = 0.f;
    for (int m = threadIdx.x; m < N_; m += 256) {
        float ec = expf(sc[m] - mc);
        float er = expf(sr[m] - mr);
        sc[m] = ec; sr[m] = er;
        tc += ec; tr += er;
    }
    tc = blockSum(tc, red);
    tr = blockSum(tr, red);

    float ic = 0.5f / tc, ir = 0.5f / tr;
    for (int m = threadIdx.x; m < N_; m += 256)
        lc[m] = sc[m] * ic + sr[m] * ir;
}

// =======================================================================================
// sim_round2 + obj_mask -> sparse CSR lists (deterministic ballot-scan compaction).
// =======================================================================================
__global__ void sim_kernel(const float* __restrict__ attn,
                           const float* __restrict__ gcls,
                           const float* __restrict__ greg,
                           int*  __restrict__ s_idx, float* __restrict__ s_val,
                           int*  __restrict__ s_cnt,
                           int*  __restrict__ o_idx, float* __restrict__ o_val,
                           int*  __restrict__ o_cnt)
{
    __shared__ float s[N_];
    __shared__ float red[8];
    __shared__ int wcS[8], wcO[8];
    int n = blockIdx.x;
    int tid = threadIdx.x;
    size_t ro = (size_t)n * N_;

    float mx = -3.4e38f;
    for (int m = tid; m < N_; m += 256) {
        float v = 0.25f * (attn[ro + m] + attn[HS_ + ro + m] +
                           attn[2 * HS_ + ro + m] + attn[3 * HS_ + ro + m]);
        s[m] = v;
        mx = fmaxf(mx, v);
    }
    mx = blockMax(mx, red);

    float S = 0.f;
    for (int m = tid; m < N_; m += 256) {
        float e  = expf(s[m] - mx);
        float me = (gcls[ro + m] > 0.75f) ? e : 0.f;
        s[m] = me;
        S += me;
    }
    S = blockSum(S, red);
    float invS = 1.f / S;

    float S2 = 0.f;
    for (int m = tid; m < N_; m += 256) S2 += s[m] * invS;
    S2 = blockSum(S2, red);
    float invS2 = 1.f / S2;

    int baseS = 0, baseO = 0;
    int lane = tid & 31, wid = tid >> 5;
    unsigned lt = (lane == 0) ? 0u : (0xffffffffu >> (32 - lane));
    for (int m0 = 0; m0 < N_; m0 += 256) {
        int m = m0 + tid;
        float me = s[m];
        bool ps = (me > 0.f);
        bool po = ps && (greg[ro + m] > 0.99f);

        unsigned bs = __ballot_sync(0xffffffffu, ps);
        unsigned bo = __ballot_sync(0xffffffffu, po);
        if (lane == 0) { wcS[wid] = __popc(bs); wcO[wid] = __popc(bo); }
        __syncthreads();
        int offS = 0, offO = 0, totS = 0, totO = 0;
#pragma unroll
        for (int w = 0; w < 8; w++) {
            int cs = wcS[w], co = wcO[w];
            if (w < wid) { offS += cs; offO += co; }
            totS += cs; totO += co;
        }
        if (ps) {
            int p = baseS + offS + __popc(bs & lt);
            s_idx[ro + p] = m;
            s_val[ro + p] = me * invS;
        }
        if (po) {
            int p = baseO + offO + __popc(bo & lt);
            o_idx[ro + p] = m;
            o_val[ro + p] = me * invS * invS2;
        }
        baseS += totS; baseO += totO;
        __syncthreads();
    }
    if (tid == 0) { s_cnt[n] = baseS; o_cnt[n] = baseO; }
}

// =======================================================================================
// Sparse pooled mix: pool[n, 0:512] = sum_j val[n,j] * pool[idx[n,j], 512:1024].
// =======================================================================================
__global__ __launch_bounds__(128)
void pool_kernel(const int* __restrict__ idx, const float* __restrict__ val,
                 const int* __restrict__ cnt, float* __restrict__ pool)
{
    int n = blockIdx.x;
    int k = cnt[n];
    size_t ro = (size_t)n * N_;
    int c = threadIdx.x * 4;

    float4 acc = make_float4(0.f, 0.f, 0.f, 0.f);
    for (int j = 0; j < k; j++) {
        int   m = idx[ro + j];
        float w = val[ro + j];
        float4 tv = *reinterpret_cast<const float4*>(pool + (size_t)m * 1024 + 512 + c);
        acc.x += w * tv.x;
        acc.y += w * tv.y;
        acc.z += w * tv.z;
        acc.w += w * tv.w;
    }
    *reinterpret_cast<float4*>(pool + (size_t)n * 1024 + c) = acc;
}

extern "C" void kernel_launch(void* const* d_in, const int* in_sizes, int n_in,
                              void* d_out, int out_size)
{
    (void)in_sizes; (void)n_in; (void)out_size;

    const float* cls_features = (const float*)d_in[0];
    const float* reg_features = (const float*)d_in[1];
    const float* cls_scores   = (const float*)d_in[2];
    const float* reg_proj_w   = (const float*)d_in[3];
    const float* qkv_cls_w    = (const float*)d_in[4];
    const float* qkv_reg_w    = (const float*)d_in[5];
    const float* l1_cls_w     = (const float*)d_in[6];
    const float* l1_cls_b     = (const float*)d_in[7];
    const float* l1_reg_w     = (const float*)d_in[8];
    const float* l1_reg_b     = (const float*)d_in[9];
    const float* l2_cls_w     = (const float*)d_in[10];
    const float* l2_cls_b     = (const float*)d_in[11];
    const float* l2_reg_w     = (const float*)d_in[12];
    const float* l2_reg_b     = (const float*)d_in[13];
    float* out = (float*)d_out;

    float *regp, *qkvc, *qkvr, *qnc, *knc, *vc, *qnr, *knr, *vr;
    float *vnfc, *vnfr, *bufA, *bufB, *enhc, *enhr, *poolc, *poolr;
    float *sr2v, *objv;
    int *sr2i, *sr2c, *obji, *objc;
    cudaGetSymbolAddress((void**)&regp,  g_regp);
    cudaGetSymbolAddress((void**)&qkvc,  g_qkv_cls);
    cudaGetSymbolAddress((void**)&qkvr,  g_qkv_reg);
    cudaGetSymbolAddress((void**)&qnc,   g_qn_cls);
    cudaGetSymbolAddress((void**)&knc,   g_kn_cls);
    cudaGetSymbolAddress((void**)&vc,    g_v_cls);
    cudaGetSymbolAddress((void**)&qnr,   g_qn_reg);
    cudaGetSymbolAddress((void**)&knr,   g_kn_reg);
    cudaGetSymbolAddress((void**)&vr,    g_v_reg);
    cudaGetSymbolAddress((void**)&vnfc,  g_vnf_cls);
    cudaGetSymbolAddress((void**)&vnfr,  g_vnf_reg);
    cudaGetSymbolAddress((void**)&bufA,  g_bufA);
    cudaGetSymbolAddress((void**)&bufB,  g_bufB);
    cudaGetSymbolAddress((void**)&sr2v,  g_sr2v);
    cudaGetSymbolAddress((void**)&sr2i,  g_sr2i);
    cudaGetSymbolAddress((void**)&sr2c,  g_sr2c);
    cudaGetSymbolAddress((void**)&objv,  g_objv);
    cudaGetSymbolAddress((void**)&obji,  g_obji);
    cudaGetSymbolAddress((void**)&objc,  g_objc);
    cudaGetSymbolAddress((void**)&enhc,  g_enh_cls);
    cudaGetSymbolAddress((void**)&enhr,  g_enh_reg);
    cudaGetSymbolAddress((void**)&poolc, g_pool_cls);
    cudaGetSymbolAddress((void**)&poolr, g_pool_reg);

    // 1) reg branch 1x1 projection
    run_gemm<true, 128>(N_, C_, D_, reg_features, D_, 0, reg_proj_w, D_, 0,
                        regp, C_, 0, 1.f, nullptr, 1);

    // 2) QKV projections
    run_gemm<true, 128>(N_, 3 * C_, C_, cls_features, C_, 0, qkv_cls_w, C_, 0,
                        qkvc, 3 * C_, 0, 1.f, nullptr, 1);
    run_gemm<true, 128>(N_, 3 * C_, C_, regp, C_, 0, qkv_reg_w, C_, 0,
                        qkvr, 3 * C_, 0, 1.f, nullptr, 1);

    // 3) split + normalize
    qkv_split_kernel<<<(N_ * H_ * 32 + 255) / 256, 256>>>(qkvc, qnc, knc, vc, vnfc, enhc);
    qkv_split_kernel<<<(N_ * H_ * 32 + 255) / 256, 256>>>(qkvr, qnr, knr, vr, vnfr, enhr);

    // 4) attention logits per head
    run_gemm<true, 128>(N_, N_, D_, qnc, D_, QS_, knc, D_, QS_, bufA, N_, HS_, 1.f, nullptr, H_);
    run_gemm<true, 128>(N_, N_, D_, qnr, D_, QS_, knr, D_, QS_, bufB, N_, HS_, 1.f, nullptr, H_);

    // 5) fused dual softmax + average
    softmax_avg_kernel<<<H_ * N_, 256>>>(bufA, bufB, cls_scores);

    // 6) gram matrices (x0.25)
    run_gemm<true, 128>(N_, N_, C_, vnfc, C_, 0, vnfc, C_, 0, bufB, N_, 0, 0.25f, nullptr, 1);
    run_gemm<true, 128>(N_, N_, C_, vnfr, C_, 0, vnfr, C_, 0, bufB + HS_, N_, 0, 0.25f, nullptr, 1);

    // 7) sim_round2 + obj_mask -> sparse
    sim_kernel<<<N_, 256>>>(bufA, bufB, bufB + HS_,
                            sr2i, sr2v, sr2c, obji, objv, objc);

    // 8) inter = attn @ v per head into enh[:, 0:256]
    run_gemm<false, 64>(N_, D_, N_, bufA, N_, HS_, vc, D_, QS_, enhc, 2 * C_, (size_t)D_, 1.f, nullptr, H_);
    run_gemm<false, 64>(N_, D_, N_, bufA, N_, HS_, vr, D_, QS_, enhr, 2 * C_, (size_t)D_, 1.f, nullptr, H_);

    // 9) l1 linears into pooled[:, 512:1024]
    run_gemm<true, 128>(N_, 2 * C_, 2 * C_, enhc, 2 * C_, 0, l1_cls_w, 2 * C_, 0,
                        poolc + 2 * C_, 4 * C_, 0, 1.f, l1_cls_b, 1);
    run_gemm<true, 128>(N_, 2 * C_, 2 * C_, enhr, 2 * C_, 0, l1_reg_w, 2 * C_, 0,
                        poolr + 2 * C_, 4 * C_, 0, 1.f, l1_reg_b, 1);

    // 10) pooled inter via sparse gather
    pool_kernel<<<N_, 128>>>(sr2i, sr2v, sr2c, poolc);
    pool_kernel<<<N_, 128>>>(obji, objv, objc, poolr);

    // 11) l2 linears -> outputs
    run_gemm<true, 128>(N_, 4 * C_, 4 * C_, poolc, 4 * C_, 0, l2_cls_w, 4 * C_, 0,
                        out, 4 * C_, 0, 1.f, l2_cls_b, 1);
    run_gemm<true, 128>(N_, 4 * C_, 4 * C_, poolr, 4 * C_, 0, l2_reg_w, 4 * C_, 0,
                        out + (size_t)N_ * 4 * C_, 4 * C_, 0, 1.f, l2_reg_b, 1);
}

// round 12
// speedup vs baseline: 2.1739x; 1.1447x over previous
#include <cuda_runtime.h>
#include <cuda_bf16.h>
#include <cstdint>
#include <cstddef>

static constexpr int    N_  = 3072;
static constexpr int    C_  = 256;
static constexpr int    H_  = 4;
static constexpr int    D_  = 64;
static constexpr size_t HS_ = (size_t)N_ * N_;
static constexpr size_t QS_ = (size_t)N_ * D_;

// ---------------- device scratch ----------------
__device__ float g_regp   [N_ * C_];
__device__ float g_qkv_cls[N_ * 3 * C_];
__device__ float g_qkv_reg[N_ * 3 * C_];
__device__ float g_qn_cls [H_ * N_ * D_];
__device__ float g_kn_cls [H_ * N_ * D_];
__device__ float g_qn_reg [H_ * N_ * D_];
__device__ float g_kn_reg [H_ * N_ * D_];
__device__ float g_vfused [H_ * N_ * 2 * D_];    // per head [k, 128] = [v_cls | v_reg]
__device__ float g_av     [H_ * N_ * 2 * D_];    // attn @ vfused result
__device__ float g_vnf_cls[N_ * C_];
__device__ float g_vnf_reg[N_ * C_];
__device__ float g_bufA[(size_t)H_ * N_ * N_];
__device__ float g_bufB[(size_t)H_ * N_ * N_];
__device__ float g_sr2v[(size_t)N_ * N_];
__device__ int   g_sr2i[(size_t)N_ * N_];
__device__ int   g_sr2c[N_];
__device__ float g_objv[(size_t)N_ * N_];
__device__ int   g_obji[(size_t)N_ * N_];
__device__ int   g_objc[N_];
__device__ float g_enh_cls[N_ * 2 * C_];
__device__ float g_enh_reg[N_ * 2 * C_];
__device__ float g_pool_cls[N_ * 4 * C_];
__device__ float g_pool_reg[N_ * 4 * C_];

// ---------------- tensor-core primitives (sm_80-era, compile on sm_100 plain) ----------------
__device__ __forceinline__ uint32_t cvta_shared(const void* p) {
    return (uint32_t)__cvta_generic_to_shared(p);
}
__device__ __forceinline__ void ldmatrix_x4(uint32_t& r0, uint32_t& r1,
                                            uint32_t& r2, uint32_t& r3, uint32_t addr) {
    asm volatile("ldmatrix.sync.aligned.m8n8.x4.shared.b16 {%0,%1,%2,%3}, [%4];"
                 : "=r"(r0), "=r"(r1), "=r"(r2), "=r"(r3) : "r"(addr));
}
__device__ __forceinline__ void mma_bf16(float* c, uint32_t a0, uint32_t a1,
                                         uint32_t a2, uint32_t a3,
                                         uint32_t b0, uint32_t b1) {
    asm volatile(
        "mma.sync.aligned.m16n8k16.row.col.f32.bf16.bf16.f32 "
        "{%0,%1,%2,%3}, {%4,%5,%6,%7}, {%8,%9}, {%0,%1,%2,%3};"
        : "+f"(c[0]), "+f"(c[1]), "+f"(c[2]), "+f"(c[3])
        : "r"(a0), "r"(a1), "r"(a2), "r"(a3), "r"(b0), "r"(b1));
}
__device__ __forceinline__ void split_bf16(float x, __nv_bfloat16& h, __nv_bfloat16& l) {
    h = __float2bfloat16_rn(x);
    l = __float2bfloat16_rn(x - __bfloat162float(h));
}

// =======================================================================================
// 3xBF16 tensor-core GEMM, BK=32 (two k16 sub-steps per stage), 128x128 CTA tile.
//   C[M,N] = alpha * A[M,K] x op(B) (+ bias[col])
//   TRANSB = true : B is [N,K] row-major;  false: B is [K,N] row-major.
// Dynamic smem: hi/lo bf16 tiles, per-sub layout identical to the validated R10 kernel
// (rows x 24 bf16, 48-byte skewed rows). REQUIRES M%128==0, N%128==0, K%32==0.
// =======================================================================================
template <bool TRANSB>
__global__ __launch_bounds__(256, 1)
void gemm_tc(int K,
             const float* __restrict__ A, int lda, size_t sA,
             const float* __restrict__ B, int ldb, size_t sB,
             float* __restrict__ C, int ldc, size_t sC,
             float alpha, const float* __restrict__ bias)
{
    constexpr int BM = 128, BN = 128, BK = 32, LDS = 24;
    constexpr int MI = 4, NI = 4;                      // WM=2 (64 rows/warp), WN=4 (32 cols/warp)
    constexpr int TSZ = BM * LDS;                      // bf16 per (buf,sub) tile = 3072
    constexpr uint32_t SUB_B = TSZ * 2;                // bytes per sub tile   = 6144
    constexpr uint32_t BUF_B = 2 * SUB_B;              // bytes per buffer     = 12288

    extern __shared__ __nv_bfloat16 sm[];
    __nv_bfloat16* AsH = sm;
    __nv_bfloat16* AsL = sm + 4 * TSZ;
    __nv_bfloat16* BsH = sm + 8 * TSZ;
    __nv_bfloat16* BsL = sm + 12 * TSZ;

    const int bz = blockIdx.z;
    A += (size_t)bz * sA;
    B += (size_t)bz * sB;
    C += (size_t)bz * sC;

    const int m0   = blockIdx.y * BM;
    const int n0   = blockIdx.x * BN;
    const int tid  = threadIdx.x;
    const int lane = tid & 31;
    const int wid  = tid >> 5;
    const int warpN = wid & 3;
    const int warpM = wid >> 2;

    // ---- staging coordinates: 4 float4 chunks each for A and B ----
    int am[4], asub[4], akin[4];
    const float* aPtr[4];
#pragma unroll
    for (int i = 0; i < 4; i++) {
        int id = tid + i * 256;
        am[i]   = id >> 3;
        int q   = id & 7;
        asub[i] = q >> 2;
        akin[i] = (q & 3) << 2;
        aPtr[i] = A + (size_t)(m0 + am[i]) * lda + (q << 2);
    }
    int bn[4], bsub[4], bkin[4];
    const float* bPtr[4];
#pragma unroll
    for (int i = 0; i < 4; i++) {
        int id = tid + i * 256;
        if (TRANSB) {
            bn[i]   = id >> 3;
            int q   = id & 7;
            bsub[i] = q >> 2;
            bkin[i] = (q & 3) << 2;
            bPtr[i] = B + (size_t)(n0 + bn[i]) * ldb + (q << 2);
        } else {
            int k   = id >> 5;                 // 0..31
            bn[i]   = (id & 31) << 2;          // n quad base
            bsub[i] = k >> 4;
            bkin[i] = k & 15;
            bPtr[i] = B + (size_t)k * ldb + n0 + bn[i];
        }
    }

    // ---- ldmatrix per-lane base addresses (buf0, sub0) — validated R10 mapping ----
    const int aRow = lane & 15, aChunk = lane >> 4;
    const int bRow = ((lane >> 4) << 3) + (lane & 7), bChunk = (lane >> 3) & 1;
    uint32_t adrAH[MI], adrAL[MI], adrBH[2], adrBL[2];
#pragma unroll
    for (int mi = 0; mi < MI; mi++) {
        int row = warpM * 64 + mi * 16 + aRow;
        adrAH[mi] = cvta_shared(AsH) + row * 48 + aChunk * 16;
        adrAL[mi] = cvta_shared(AsL) + row * 48 + aChunk * 16;
    }
#pragma unroll
    for (int p = 0; p < 2; p++) {
        int row = warpN * 32 + p * 16 + bRow;
        adrBH[p] = cvta_shared(BsH) + row * 48 + bChunk * 16;
        adrBL[p] = cvta_shared(BsL) + row * 48 + bChunk * 16;
    }

    float acc[MI][NI][4];
#pragma unroll
    for (int mi = 0; mi < MI; mi++)
#pragma unroll
        for (int ni = 0; ni < NI; ni++)
#pragma unroll
            for (int j = 0; j < 4; j++) acc[mi][ni][j] = 0.f;

    float4 avr[4], bvr[4];
    auto ldg = [&](int k0) {
#pragma unroll
        for (int i = 0; i < 4; i++) avr[i] = *reinterpret_cast<const float4*>(aPtr[i] + k0);
        if (TRANSB) {
#pragma unroll
            for (int i = 0; i < 4; i++) bvr[i] = *reinterpret_cast<const float4*>(bPtr[i] + k0);
        } else {
#pragma unroll
            for (int i = 0; i < 4; i++)
                bvr[i] = *reinterpret_cast<const float4*>(bPtr[i] + (size_t)k0 * ldb);
        }
    };
    auto sts = [&](int buf) {
#pragma unroll
        for (int i = 0; i < 4; i++) {
            // A
            {
                __nv_bfloat16 h0, h1, h2, h3, l0, l1, l2, l3;
                split_bf16(avr[i].x, h0, l0); split_bf16(avr[i].y, h1, l1);
                split_bf16(avr[i].z, h2, l2); split_bf16(avr[i].w, h3, l3);
                int o = ((buf * 2 + asub[i]) * BM + am[i]) * LDS + akin[i];
                __nv_bfloat162* ph = reinterpret_cast<__nv_bfloat162*>(&AsH[o]);
                __nv_bfloat162* pl = reinterpret_cast<__nv_bfloat162*>(&AsL[o]);
                ph[0] = __nv_bfloat162(h0, h1); ph[1] = __nv_bfloat162(h2, h3);
                pl[0] = __nv_bfloat162(l0, l1); pl[1] = __nv_bfloat162(l2, l3);
            }
            // B
            {
                __nv_bfloat16 h0, h1, h2, h3, l0, l1, l2, l3;
                split_bf16(bvr[i].x, h0, l0); split_bf16(bvr[i].y, h1, l1);
                split_bf16(bvr[i].z, h2, l2); split_bf16(bvr[i].w, h3, l3);
                if (TRANSB) {
                    int o = ((buf * 2 + bsub[i]) * BN + bn[i]) * LDS + bkin[i];
                    __nv_bfloat162* ph = reinterpret_cast<__nv_bfloat162*>(&BsH[o]);
                    __nv_bfloat162* pl = reinterpret_cast<__nv_bfloat162*>(&BsL[o]);
                    ph[0] = __nv_bfloat162(h0, h1); ph[1] = __nv_bfloat162(h2, h3);
                    pl[0] = __nv_bfloat162(l0, l1); pl[1] = __nv_bfloat162(l2, l3);
                } else {
                    int ob = (buf * 2 + bsub[i]) * BN;
                    BsH[(ob + bn[i] + 0) * LDS + bkin[i]] = h0;
                    BsH[(ob + bn[i] + 1) * LDS + bkin[i]] = h1;
                    BsH[(ob + bn[i] + 2) * LDS + bkin[i]] = h2;
                    BsH[(ob + bn[i] + 3) * LDS + bkin[i]] = h3;
                    BsL[(ob + bn[i] + 0) * LDS + bkin[i]] = l0;
                    BsL[(ob + bn[i] + 1) * LDS + bkin[i]] = l1;
                    BsL[(ob + bn[i] + 2) * LDS + bkin[i]] = l2;
                    BsL[(ob + bn[i] + 3) * LDS + bkin[i]] = l3;
                }
            }
        }
    };

    ldg(0);
    sts(0);
    __syncthreads();

    const int S = K >> 5;
    int buf = 0;
    for (int s = 0; s < S; s++) {
        const bool has_next = (s + 1) < S;
        if (has_next) ldg((s + 1) << 5);

#pragma unroll
        for (int sub = 0; sub < 2; sub++) {
            const uint32_t off = (uint32_t)buf * BUF_B + (uint32_t)sub * SUB_B;
            uint32_t aH[MI][4], aL[MI][4], bH[NI][2], bL[NI][2];
#pragma unroll
            for (int mi = 0; mi < MI; mi++) {
                ldmatrix_x4(aH[mi][0], aH[mi][1], aH[mi][2], aH[mi][3], adrAH[mi] + off);
                ldmatrix_x4(aL[mi][0], aL[mi][1], aL[mi][2], aL[mi][3], adrAL[mi] + off);
            }
#pragma unroll
            for (int p = 0; p < 2; p++) {
                uint32_t r0, r1, r2, r3;
                ldmatrix_x4(r0, r1, r2, r3, adrBH[p] + off);
                bH[2 * p][0] = r0; bH[2 * p][1] = r1;
                bH[2 * p + 1][0] = r2; bH[2 * p + 1][1] = r3;
                ldmatrix_x4(r0, r1, r2, r3, adrBL[p] + off);
                bL[2 * p][0] = r0; bL[2 * p][1] = r1;
                bL[2 * p + 1][0] = r2; bL[2 * p + 1][1] = r3;
            }
#pragma unroll
            for (int mi = 0; mi < MI; mi++)
#pragma unroll
                for (int ni = 0; ni < NI; ni++) {
                    mma_bf16(acc[mi][ni], aH[mi][0], aH[mi][1], aH[mi][2], aH[mi][3],
                             bH[ni][0], bH[ni][1]);
                    mma_bf16(acc[mi][ni], aH[mi][0], aH[mi][1], aH[mi][2], aH[mi][3],
                             bL[ni][0], bL[ni][1]);
                    mma_bf16(acc[mi][ni], aL[mi][0], aL[mi][1], aL[mi][2], aL[mi][3],
                             bH[ni][0], bH[ni][1]);
                }
        }

        if (has_next) {
            sts(buf ^ 1);
            __syncthreads();
            buf ^= 1;
        }
    }

    // ---- epilogue: m16n8 D layout (rows g, g+8; cols 2t, 2t+1) — validated ----
    const int g = lane >> 2, t = lane & 3;
#pragma unroll
    for (int mi = 0; mi < MI; mi++) {
#pragma unroll
        for (int ni = 0; ni < NI; ni++) {
            int col = n0 + warpN * 32 + ni * 8 + t * 2;
            int r0  = m0 + warpM * 64 + mi * 16 + g;
            float2 o0, o1;
            o0.x = alpha * acc[mi][ni][0];
            o0.y = alpha * acc[mi][ni][1];
            o1.x = alpha * acc[mi][ni][2];
            o1.y = alpha * acc[mi][ni][3];
            if (bias) {
                float2 bv = *reinterpret_cast<const float2*>(bias + col);
                o0.x += bv.x; o0.y += bv.y;
                o1.x += bv.x; o1.y += bv.y;
            }
            *reinterpret_cast<float2*>(C + (size_t)r0 * ldc + col)       = o0;
            *reinterpret_cast<float2*>(C + (size_t)(r0 + 8) * ldc + col) = o1;
        }
    }
}

static constexpr int GEMM_SMEM = 16 * 128 * 24 * 2;   // 98304 bytes

template <bool TRANSB>
static void run_gemm(int M, int N, int K,
                     const float* A, int lda, size_t sA,
                     const float* B, int ldb, size_t sB,
                     float* C, int ldc, size_t sC,
                     float alpha, const float* bias, int batch)
{
    dim3 grid(N / 128, M / 128, batch);
    gemm_tc<TRANSB><<<grid, 256, GEMM_SMEM>>>(K, A, lda, sA, B, ldb, sB,
                                              C, ldc, sC, alpha, bias);
}

// ---------------- block reduction helpers ----------------
__device__ __forceinline__ float warpMax(float v) {
#pragma unroll
    for (int o = 16; o; o >>= 1) v = fmaxf(v, __shfl_xor_sync(0xffffffffu, v, o));
    return v;
}
__device__ __forceinline__ float warpSum(float v) {
#pragma unroll
    for (int o = 16; o; o >>= 1) v += __shfl_xor_sync(0xffffffffu, v, o);
    return v;
}
__device__ __forceinline__ float blockMax(float v, float* red) {
    v = warpMax(v);
    if ((threadIdx.x & 31) == 0) red[threadIdx.x >> 5] = v;
    __syncthreads();
    float r = red[0];
#pragma unroll
    for (int i = 1; i < 8; i++) r = fmaxf(r, red[i]);
    __syncthreads();
    return r;
}
__device__ __forceinline__ float blockSum(float v, float* red) {
    v = warpSum(v);
    if ((threadIdx.x & 31) == 0) red[threadIdx.x >> 5] = v;
    __syncthreads();
    float r = red[0];
#pragma unroll
    for (int i = 1; i < 8; i++) r += red[i];
    __syncthreads();
    return r;
}

// ============================ QKV split + L2-normalize ============================
// Also writes raw v into vfused[h][n][coloff + d] ([k,128] panel per head) and into
// the 'ori' half of enh.
__global__ void qkv_split_kernel(const float* __restrict__ qkv,
                                 float* __restrict__ qn, float* __restrict__ kn,
                                 float* __restrict__ vf, int coloff,
                                 float* __restrict__ vnf,
                                 float* __restrict__ enh)
{
    int w = (blockIdx.x * blockDim.x + threadIdx.x) >> 5;
    if (w >= N_ * H_) return;
    int lane = threadIdx.x & 31;
    int h = w & 3;
    int n = w >> 2;

    const float* src = qkv + (size_t)n * (3 * C_) + h * D_;
    float q0 = src[lane],            q1 = src[lane + 32];
    float k0 = src[C_ + lane],       k1 = src[C_ + lane + 32];
    float v0 = src[2 * C_ + lane],   v1 = src[2 * C_ + lane + 32];

    float sq = warpSum(q0 * q0 + q1 * q1);
    float sk = warpSum(k0 * k0 + k1 * k1);
    float sv = warpSum(v0 * v0 + v1 * v1);
    float iq = 1.f / fmaxf(sqrtf(sq), 1e-6f);
    float ik = 1.f / fmaxf(sqrtf(sk), 1e-6f);
    float iv = 1.f / fmaxf(sqrtf(sv), 1e-6f);

    size_t ho = ((size_t)h * N_ + n) * D_;
    qn[ho + lane] = q0 * iq;  qn[ho + lane + 32] = q1 * iq;
    kn[ho + lane] = k0 * ik;  kn[ho + lane + 32] = k1 * ik;

    size_t vo = ((size_t)h * N_ + n) * (2 * D_) + coloff;
    vf[vo + lane] = v0;       vf[vo + lane + 32] = v1;

    size_t fo = (size_t)n * C_ + h * D_;
    vnf[fo + lane] = v0 * iv; vnf[fo + lane + 32] = v1 * iv;

    size_t eo = (size_t)n * (2 * C_) + C_ + h * D_;
    enh[eo + lane] = v0;      enh[eo + lane + 32] = v1;
}

// ============================ fused dual softmax + average ============================
__global__ void softmax_avg_kernel(float* __restrict__ lc_all,
                                   const float* __restrict__ lr_all,
                                   const float* __restrict__ scores)
{
    __shared__ float sc[N_];
    __shared__ float sr[N_];
    __shared__ float red[8];
    size_t base = (size_t)blockIdx.x * N_;
    float* lc = lc_all + base;
    const float* lr = lr_all + base;

    float mc = -3.4e38f, mr = -3.4e38f;
    for (int m = threadIdx.x; m < N_; m += 256) {
        float xc = lc[m] * (25.0f * scores[m]);
        float xr = lr[m] * 25.0f;
        sc[m] = xc; sr[m] = xr;
        mc = fmaxf(mc, xc); mr = fmaxf(mr, xr);
    }
    mc = blockMax(mc, red);
    mr = blockMax(mr, red);

    float tc = 0.f, tr = 0.f;
    for (int m = threadIdx.x; m < N_; m += 256) {
        float ec = expf(sc[m] - mc);
        float er = expf(sr[m] - mr);
        sc[m] = ec; sr[m] = er;
        tc += ec; tr += er;
    }
    tc = blockSum(tc, red);
    tr = blockSum(tr, red);

    float ic = 0.5f / tc, ir = 0.5f / tr;
    for (int m = threadIdx.x; m < N_; m += 256)
        lc[m] = sc[m] * ic + sr[m] * ir;
}

// ============== sim_round2 + obj_mask -> sparse CSR (deterministic) ==============
__global__ void sim_kernel(const float* __restrict__ attn,
                           const float* __restrict__ gcls,
                           const float* __restrict__ greg,
                           int*  __restrict__ s_idx, float* __restrict__ s_val,
                           int*  __restrict__ s_cnt,
                           int*  __restrict__ o_idx, float* __restrict__ o_val,
                           int*  __restrict__ o_cnt)
{
    __shared__ float s[N_];
    __shared__ float red[8];
    __shared__ int wcS[8], wcO[8];
    int n = blockIdx.x;
    int tid = threadIdx.x;
    size_t ro = (size_t)n * N_;

    float mx = -3.4e38f;
    for (int m = tid; m < N_; m += 256) {
        float v = 0.25f * (attn[ro + m] + attn[HS_ + ro + m] +
                           attn[2 * HS_ + ro + m] + attn[3 * HS_ + ro + m]);
        s[m] = v;
        mx = fmaxf(mx, v);
    }
    mx = blockMax(mx, red);

    float S = 0.f;
    for (int m = tid; m < N_; m += 256) {
        float e  = expf(s[m] - mx);
        float me = (gcls[ro + m] > 0.75f) ? e : 0.f;
        s[m] = me;
        S += me;
    }
    S = blockSum(S, red);
    float invS = 1.f / S;

    float S2 = 0.f;
    for (int m = tid; m < N_; m += 256) S2 += s[m] * invS;
    S2 = blockSum(S2, red);
    float invS2 = 1.f / S2;

    int baseS = 0, baseO = 0;
    int lane = tid & 31, wid = tid >> 5;
    unsigned lt = (lane == 0) ? 0u : (0xffffffffu >> (32 - lane));
    for (int m0 = 0; m0 < N_; m0 += 256) {
        int m = m0 + tid;
        float me = s[m];
        bool ps = (me > 0.f);
        bool po = ps && (greg[ro + m] > 0.99f);

        unsigned bs = __ballot_sync(0xffffffffu, ps);
        unsigned bo = __ballot_sync(0xffffffffu, po);
        if (lane == 0) { wcS[wid] = __popc(bs); wcO[wid] = __popc(bo); }
        __syncthreads();
        int offS = 0, offO = 0, totS = 0, totO = 0;
#pragma unroll
        for (int w = 0; w < 8; w++) {
            int cs = wcS[w], co = wcO[w];
            if (w < wid) { offS += cs; offO += co; }
            totS += cs; totO += co;
        }
        if (ps) {
            int p = baseS + offS + __popc(bs & lt);
            s_idx[ro + p] = m;
            s_val[ro + p] = me * invS;
        }
        if (po) {
            int p = baseO + offO + __popc(bo & lt);
            o_idx[ro + p] = m;
            o_val[ro + p] = me * invS * invS2;
        }
        baseS += totS; baseO += totO;
        __syncthreads();
    }
    if (tid == 0) { s_cnt[n] = baseS; o_cnt[n] = baseO; }
}

// ============== sparse pooled mix ==============
__global__ __launch_bounds__(128)
void pool_kernel(const int* __restrict__ idx, const float* __restrict__ val,
                 const int* __restrict__ cnt, float* __restrict__ pool)
{
    int n = blockIdx.x;
    int k = cnt[n];
    size_t ro = (size_t)n * N_;
    int c = threadIdx.x * 4;

    float4 acc = make_float4(0.f, 0.f, 0.f, 0.f);
    for (int j = 0; j < k; j++) {
        int   m = idx[ro + j];
        float w = val[ro + j];
        float4 tv = *reinterpret_cast<const float4*>(pool + (size_t)m * 1024 + 512 + c);
        acc.x += w * tv.x;
        acc.y += w * tv.y;
        acc.z += w * tv.z;
        acc.w += w * tv.w;
    }
    *reinterpret_cast<float4*>(pool + (size_t)n * 1024 + c) = acc;
}

// ============== scatter attn@V result into enh inter halves ==============
// av[h][n][0:64] -> enh_cls[n][h*64 .. h*64+63]; av[h][n][64:128] -> enh_reg likewise.
__global__ __launch_bounds__(256)
void scatter_av_kernel(const float* __restrict__ av,
                       float* __restrict__ ec, float* __restrict__ er)
{
    int t = blockIdx.x * 256 + threadIdx.x;      // one float4 each; total H*N*32
    int q = t & 31;
    int n = (t >> 5) & (N_ - 1);                 // N_ = 3072 not pow2 -> use div
    n = (t >> 5) % N_;
    int h = t / (N_ * 32);
    float4 v = *reinterpret_cast<const float4*>(av + ((size_t)h * N_ + n) * 128 + q * 4);
    if (q < 16)
        *reinterpret_cast<float4*>(ec + (size_t)n * 512 + h * 64 + q * 4) = v;
    else
        *reinterpret_cast<float4*>(er + (size_t)n * 512 + h * 64 + (q - 16) * 4) = v;
}

extern "C" void kernel_launch(void* const* d_in, const int* in_sizes, int n_in,
                              void* d_out, int out_size)
{
    (void)in_sizes; (void)n_in; (void)out_size;

    cudaFuncSetAttribute(gemm_tc<true>,  cudaFuncAttributeMaxDynamicSharedMemorySize, GEMM_SMEM);
    cudaFuncSetAttribute(gemm_tc<false>, cudaFuncAttributeMaxDynamicSharedMemorySize, GEMM_SMEM);

    const float* cls_features = (const float*)d_in[0];
    const float* reg_features = (const float*)d_in[1];
    const float* cls_scores   = (const float*)d_in[2];
    const float* reg_proj_w   = (const float*)d_in[3];
    const float* qkv_cls_w    = (const float*)d_in[4];
    const float* qkv_reg_w    = (const float*)d_in[5];
    const float* l1_cls_w     = (const float*)d_in[6];
    const float* l1_cls_b     = (const float*)d_in[7];
    const float* l1_reg_w     = (const float*)d_in[8];
    const float* l1_reg_b     = (const float*)d_in[9];
    const float* l2_cls_w     = (const float*)d_in[10];
    const float* l2_cls_b     = (const float*)d_in[11];
    const float* l2_reg_w     = (const float*)d_in[12];
    const float* l2_reg_b     = (const float*)d_in[13];
    float* out = (float*)d_out;

    float *regp, *qkvc, *qkvr, *qnc, *knc, *qnr, *knr, *vfused, *av;
    float *vnfc, *vnfr, *bufA, *bufB, *enhc, *enhr, *poolc, *poolr;
    float *sr2v, *objv;
    int *sr2i, *sr2c, *obji, *objc;
    cudaGetSymbolAddress((void**)&regp,   g_regp);
    cudaGetSymbolAddress((void**)&qkvc,   g_qkv_cls);
    cudaGetSymbolAddress((void**)&qkvr,   g_qkv_reg);
    cudaGetSymbolAddress((void**)&qnc,    g_qn_cls);
    cudaGetSymbolAddress((void**)&knc,    g_kn_cls);
    cudaGetSymbolAddress((void**)&qnr,    g_qn_reg);
    cudaGetSymbolAddress((void**)&knr,    g_kn_reg);
    cudaGetSymbolAddress((void**)&vfused, g_vfused);
    cudaGetSymbolAddress((void**)&av,     g_av);
    cudaGetSymbolAddress((void**)&vnfc,   g_vnf_cls);
    cudaGetSymbolAddress((void**)&vnfr,   g_vnf_reg);
    cudaGetSymbolAddress((void**)&bufA,   g_bufA);
    cudaGetSymbolAddress((void**)&bufB,   g_bufB);
    cudaGetSymbolAddress((void**)&sr2v,   g_sr2v);
    cudaGetSymbolAddress((void**)&sr2i,   g_sr2i);
    cudaGetSymbolAddress((void**)&sr2c,   g_sr2c);
    cudaGetSymbolAddress((void**)&objv,   g_objv);
    cudaGetSymbolAddress((void**)&obji,   g_obji);
    cudaGetSymbolAddress((void**)&objc,   g_objc);
    cudaGetSymbolAddress((void**)&enhc,   g_enh_cls);
    cudaGetSymbolAddress((void**)&enhr,   g_enh_reg);
    cudaGetSymbolAddress((void**)&poolc,  g_pool_cls);
    cudaGetSymbolAddress((void**)&poolr,  g_pool_reg);

    // 1) reg branch 1x1 projection: [N,64]@[256,64]^T (K=64, %32 ok)
    run_gemm<true>(N_, C_, D_, reg_features, D_, 0, reg_proj_w, D_, 0,
                   regp, C_, 0, 1.f, nullptr, 1);

    // 2) QKV projections
    run_gemm<true>(N_, 3 * C_, C_, cls_features, C_, 0, qkv_cls_w, C_, 0,
                   qkvc, 3 * C_, 0, 1.f, nullptr, 1);
    run_gemm<true>(N_, 3 * C_, C_, regp, C_, 0, qkv_reg_w, C_, 0,
                   qkvr, 3 * C_, 0, 1.f, nullptr, 1);

    // 3) split + normalize (v -> fused [k,128] panels; cls cols 0-63, reg cols 64-127)
    qkv_split_kernel<<<(N_ * H_ * 32 + 255) / 256, 256>>>(qkvc, qnc, knc, vfused, 0,  vnfc, enhc);
    qkv_split_kernel<<<(N_ * H_ * 32 + 255) / 256, 256>>>(qkvr, qnr, knr, vfused, 64, vnfr, enhr);

    // 4) attention logits per head (batched)
    run_gemm<true>(N_, N_, D_, qnc, D_, QS_, knc, D_, QS_, bufA, N_, HS_, 1.f, nullptr, H_);
    run_gemm<true>(N_, N_, D_, qnr, D_, QS_, knr, D_, QS_, bufB, N_, HS_, 1.f, nullptr, H_);

    // 5) fused dual softmax + average (in place in bufA)
    softmax_avg_kernel<<<H_ * N_, 256>>>(bufA, bufB, cls_scores);

    // 6) gram matrices (x0.25)
    run_gemm<true>(N_, N_, C_, vnfc, C_, 0, vnfc, C_, 0, bufB, N_, 0, 0.25f, nullptr, 1);
    run_gemm<true>(N_, N_, C_, vnfr, C_, 0, vnfr, C_, 0, bufB + HS_, N_, 0, 0.25f, nullptr, 1);

    // 7) sim_round2 + obj_mask -> sparse
    sim_kernel<<<N_, 256>>>(bufA, bufB, bufB + HS_, sr2i, sr2v, sr2c, obji, objv, objc);

    // 8) fused attn @ [v_cls|v_reg] per head (one launch), then scatter into enh halves
    run_gemm<false>(N_, 128, N_, bufA, N_, HS_, vfused, 128, (size_t)N_ * 128,
                    av, 128, (size_t)N_ * 128, 1.f, nullptr, H_);
    scatter_av_kernel<<<(H_ * N_ * 32) / 256, 256>>>(av, enhc, enhr);

    // 9) l1 linears into pooled[:, 512:1024]
    run_gemm<true>(N_, 2 * C_, 2 * C_, enhc, 2 * C_, 0, l1_cls_w, 2 * C_, 0,
                   poolc + 2 * C_, 4 * C_, 0, 1.f, l1_cls_b, 1);
    run_gemm<true>(N_, 2 * C_, 2 * C_, enhr, 2 * C_, 0, l1_reg_w, 2 * C_, 0,
                   poolr + 2 * C_, 4 * C_, 0, 1.f, l1_reg_b, 1);

    // 10) pooled inter via sparse gather
    pool_kernel<<<N_, 128>>>(sr2i, sr2v, sr2c, poolc);
    pool_kernel<<<N_, 128>>>(obji, objv, objc, poolr);

    // 11) l2 linears -> outputs
    run_gemm<true>(N_, 4 * C_, 4 * C_, poolc, 4 * C_, 0, l2_cls_w, 4 * C_, 0,
                   out, 4 * C_, 0, 1.f, l2_cls_b, 1);
    run_gemm<true>(N_, 4 * C_, 4 * C_, poolr, 4 * C_, 0, l2_reg_w, 4 * C_, 0,
                   out + (size_t)N_ * 4 * C_, 4 * C_, 0, 1.f, l2_reg_b, 1);
}